// round 11
// baseline (speedup 1.0000x reference)
#include <cuda_runtime.h>
#include <cuda_fp16.h>
#include <cstdint>

#define DIMK 768
#define MROWS 4096
#define VCOLS 50257
#define VPAD 50304            // padded vocab = 262 * 192 (even)
#define BM 128
#define BN 192
#define KC 64                 // K elems per stage: 64 half = 128B rows (SW128)
#define NCH (DIMK / KC)       // 12
#define NT2 (VPAD / BN)       // 262 n-tiles
#define NMB (MROWS / BM)      // 32 m-blocks
#define TOT_TILES (NMB * NT2) // 8384
#define A_STAGE_BYTES (BM * 128)   // 16 KB
#define B_STAGE_BYTES (BN * 128)   // 24 KB
#define STAGE_BYTES (A_STAGE_BYTES + B_STAGE_BYTES)
#define DSMEM (3 * STAGE_BYTES)    // 120 KB
#define NCTA 148                   // 1 per SM, all resident
#define NTHR 320                   // 256 MMA + 64 fixup

// Scratch (device globals: allocation-free rule)
__device__ __half g_xn[(size_t)MROWS * DIMK];
__device__ __half g_wn[(size_t)VPAD * DIMK];
__device__ __half g_scr[(size_t)MROWS * VPAD];        // fp16 logits scratch
__device__ float g_partials[(size_t)NT2 * MROWS];     // [ntile][row] transposed
__device__ float g_lse[MROWS];
__device__ int g_tile;
__device__ int g_fixrow;
__device__ int g_done[NMB];
__device__ int g_ready[NMB];

__device__ __forceinline__ uint32_t smem_u32(const void* p) {
    uint32_t a;
    asm("{ .reg .u64 t; cvta.to.shared.u64 t, %1; cvt.u32.u64 %0, t; }" : "=r"(a) : "l"(p));
    return a;
}
__device__ __forceinline__ uint32_t swz(uint32_t x) { return x ^ ((x >> 3) & 0x70); }
__device__ __forceinline__ void nb_sync() {            // barrier 1, MMA threads only
    asm volatile("bar.sync 1, %0;" :: "n"(256) : "memory");
}

template <int N>
__device__ __forceinline__ void cpwait() {
    asm volatile("cp.async.wait_group %0;" :: "n"(N) : "memory");
}
__device__ __forceinline__ void cpcommit() {
    asm volatile("cp.async.commit_group;" ::: "memory");
}
__device__ __forceinline__ void cpasync16(uint32_t s, const void* g) {
    asm volatile("cp.async.cg.shared.global [%0], [%1], 16;" :: "r"(s), "l"(g) : "memory");
}
__device__ __forceinline__ void ldm_x4(uint32_t& r0, uint32_t& r1, uint32_t& r2,
                                       uint32_t& r3, uint32_t addr) {
    asm volatile("ldmatrix.sync.aligned.m8n8.x4.shared.b16 {%0,%1,%2,%3}, [%4];"
                 : "=r"(r0), "=r"(r1), "=r"(r2), "=r"(r3) : "r"(addr));
}

__global__ void reset_kernel() {
    if (threadIdx.x == 0) { g_tile = 0; g_fixrow = 0; }
    if (threadIdx.x < NMB) { g_done[threadIdx.x] = 0; g_ready[threadIdx.x] = 0; }
}

// ---------------------------------------------------------------------------
// Row L2-normalize: 4 rows/block, 64 threads/row, single pass, fp16 out.
// ---------------------------------------------------------------------------
__global__ void __launch_bounds__(256) norm_rows_kernel(const float* __restrict__ x,
                                                        const float* __restrict__ wv) {
    const int tid = threadIdx.x;
    const int sub = tid >> 6;
    const int l64 = tid & 63;
    const int row = blockIdx.x * 4 + sub;

    const float* p;
    __half* q;
    bool zero = false;
    if (row < MROWS) {
        p = x + (size_t)row * DIMK;
        q = g_xn + (size_t)row * DIMK;
    } else {
        int r = row - MROWS;
        q = g_wn + (size_t)r * DIMK;
        p = wv + (size_t)r * DIMK;
        zero = (r >= VCOLS);
    }

    float4 v[3];
    float s = 0.f;
    if (!zero) {
#pragma unroll
        for (int j = 0; j < 3; j++) {
            v[j] = *(const float4*)(p + j * 256 + l64 * 4);
            s += v[j].x * v[j].x + v[j].y * v[j].y + v[j].z * v[j].z + v[j].w * v[j].w;
        }
    } else {
#pragma unroll
        for (int j = 0; j < 3; j++) v[j] = make_float4(0.f, 0.f, 0.f, 0.f);
    }
    for (int o = 16; o; o >>= 1) s += __shfl_xor_sync(0xffffffffu, s, o);
    __shared__ float sm[8];
    if ((tid & 31) == 0) sm[tid >> 5] = s;
    __syncthreads();
    const float tot = sm[sub * 2] + sm[sub * 2 + 1];
    const float scale = zero ? 0.f : (1.f / fmaxf(sqrtf(tot), 1e-12f));

#pragma unroll
    for (int j = 0; j < 3; j++) {
        __half2 h0 = __floats2half2_rn(v[j].x * scale, v[j].y * scale);
        __half2 h1 = __floats2half2_rn(v[j].z * scale, v[j].w * scale);
        uint2 pk = make_uint2(*(uint32_t*)&h0, *(uint32_t*)&h1);
        *(uint2*)(q + j * 256 + l64 * 4) = pk;
    }
}

// ---------------------------------------------------------------------------
// Warp-level fixup of one row (32 lanes).
// ---------------------------------------------------------------------------
__device__ void fixup_row(float* __restrict__ out, const float* __restrict__ bias,
                          int row, int lane) {
    const float lse = g_lse[row];
    const __half* ps = g_scr + (size_t)row * VPAD;
    float* po = out + (size_t)row * VCOLS;

    const int head = (4 - (int)(((uintptr_t)po >> 2) & 3)) & 3;
    if (lane < head) po[lane] = __half2float(__ldcs(ps + lane)) - lse + __ldg(bias + lane);
    const int count4 = (VCOLS - head) >> 2;
    const int tail0 = head + count4 * 4;
    if (lane < VCOLS - tail0) {
        const int col = tail0 + lane;
        po[col] = __half2float(__ldcs(ps + col)) - lse + __ldg(bias + col);
    }
    if ((head & 1) == 0) {
#pragma unroll 2
        for (int i = lane; i < count4; i += 32) {
            const int col = head + i * 4;
            float2 a = __half22float2(__ldcs((const __half2*)(ps + col)));
            float2 b = __half22float2(__ldcs((const __half2*)(ps + col + 2)));
            float4 o4;
            o4.x = a.x - lse + __ldg(bias + col);
            o4.y = a.y - lse + __ldg(bias + col + 1);
            o4.z = b.x - lse + __ldg(bias + col + 2);
            o4.w = b.y - lse + __ldg(bias + col + 3);
            *(float4*)(po + col) = o4;
        }
    } else {
#pragma unroll 2
        for (int i = lane; i < count4; i += 32) {
            const int col = head + i * 4;
            float4 o4;
            o4.x = __half2float(__ldcs(ps + col))     - lse + __ldg(bias + col);
            o4.y = __half2float(__ldcs(ps + col + 1)) - lse + __ldg(bias + col + 1);
            o4.z = __half2float(__ldcs(ps + col + 2)) - lse + __ldg(bias + col + 2);
            o4.w = __half2float(__ldcs(ps + col + 3)) - lse + __ldg(bias + col + 3);
            *(float4*)(po + col) = o4;
        }
    }
}

// ---------------------------------------------------------------------------
// Warp-specialized persistent kernel: 8 MMA warps (tid<256) + 2 fixup warps.
// Tile 128x192 (2x4 warps, 64x48 warp tile), 3-stage cp.async, mb-major.
// ---------------------------------------------------------------------------
__global__ void __launch_bounds__(NTHR, 1) gemm_kernel(float* __restrict__ out,
                                                       const float* __restrict__ bias) {
    extern __shared__ __align__(1024) char smem[];
    __shared__ int s_t, s_old;

    const int tid = threadIdx.x;

    // ===================== Fixup warps (tid >= 256) =====================
    if (tid >= 256) {
        const int lane = tid & 31;
        for (;;) {
            int row;
            if (lane == 0) row = atomicAdd(&g_fixrow, 1);
            row = __shfl_sync(0xffffffffu, row, 0);
            if (row >= MROWS) return;
            const int mb = row >> 7;
            if (lane == 0) {
                while (atomicAdd(&g_ready[mb], 0) == 0) __nanosleep(512);
            }
            __syncwarp();
            __threadfence();
            fixup_row(out, bias, row, lane);
        }
    }

    // ===================== MMA warps (tid < 256) ========================
    const int w = tid >> 5, lane = tid & 31;
    const int wm = w >> 2, wn = w & 3;         // 2 x 4 warp grid
    const uint32_t sbase = smem_u32(smem);

    uint32_t aoff[4], boff[3];
#pragma unroll
    for (int mt = 0; mt < 4; mt++)
        aoff[mt] = (uint32_t)(wm * 64 + mt * 16 + (lane & 15)) * 128;
#pragma unroll
    for (int p = 0; p < 3; p++)
        boff[p] = (uint32_t)(wn * 48 + p * 16 + (lane & 7) + ((lane >> 4) & 1) * 8) * 128;
    const uint32_t acol = ((uint32_t)(lane >> 4)) * 16;
    const uint32_t bcol = ((uint32_t)((lane >> 3) & 1)) * 16;
    const int g = lane >> 2, tig = lane & 3;

    for (;;) {
        if (tid == 0) s_t = atomicAdd(&g_tile, 1);
        nb_sync();
        const int t = s_t;
        if (t >= TOT_TILES) return;
        const int mb = t / NT2;
        const int nt_tile = t - mb * NT2;
        const int m0 = mb * BM;
        const int n0 = nt_tile * BN;

        const __half* Ag = g_xn + (size_t)m0 * DIMK;
        const __half* Bg = g_wn + (size_t)n0 * DIMK;

        auto load_chunk = [&](int slot, int k0) {
            uint32_t sA = sbase + slot * STAGE_BYTES;
            uint32_t sB = sA + A_STAGE_BYTES;
#pragma unroll
            for (int i = 0; i < 4; i++) {          // A: 1024 segs
                int s = i * 256 + tid;
                int row = s >> 3, seg = s & 7;
                cpasync16(sA + swz(row * 128 + seg * 16),
                          Ag + (size_t)row * DIMK + k0 + seg * 8);
            }
#pragma unroll
            for (int i = 0; i < 6; i++) {          // B: 1536 segs
                int s = i * 256 + tid;
                int row = s >> 3, seg = s & 7;
                cpasync16(sB + swz(row * 128 + seg * 16),
                          Bg + (size_t)row * DIMK + k0 + seg * 8);
            }
            cpcommit();
        };

        float acc[4][6][4];
#pragma unroll
        for (int a = 0; a < 4; a++)
#pragma unroll
            for (int b = 0; b < 6; b++)
#pragma unroll
                for (int c2 = 0; c2 < 4; c2++) acc[a][b][c2] = 0.f;

        uint32_t afr[2][4][4], bfr[2][3][4];

        load_chunk(0, 0);
        load_chunk(1, KC);

#pragma unroll 1
        for (int c = 0; c < NCH; c++) {
            if (c + 2 < NCH) load_chunk((c + 2) % 3, (c + 2) * KC);
            if (c <= NCH - 3) cpwait<2>();
            else if (c == NCH - 2) cpwait<1>();
            else cpwait<0>();
            nb_sync();

            const uint32_t sA = sbase + (c % 3) * STAGE_BYTES;
            const uint32_t sB = sA + A_STAGE_BYTES;

#pragma unroll
            for (int mt = 0; mt < 4; mt++)
                ldm_x4(afr[0][mt][0], afr[0][mt][1], afr[0][mt][2], afr[0][mt][3],
                       sA + swz(aoff[mt] + acol));
#pragma unroll
            for (int p = 0; p < 3; p++)
                ldm_x4(bfr[0][p][0], bfr[0][p][1], bfr[0][p][2], bfr[0][p][3],
                       sB + swz(boff[p] + bcol));

#pragma unroll
            for (int step = 0; step < KC / 16; step++) {
                const int cur = step & 1;
                if (step < KC / 16 - 1) {
                    const int nxt = cur ^ 1;
                    const uint32_t kb = (uint32_t)(step + 1) * 32;
#pragma unroll
                    for (int mt = 0; mt < 4; mt++)
                        ldm_x4(afr[nxt][mt][0], afr[nxt][mt][1], afr[nxt][mt][2], afr[nxt][mt][3],
                               sA + swz(aoff[mt] + kb + acol));
#pragma unroll
                    for (int p = 0; p < 3; p++)
                        ldm_x4(bfr[nxt][p][0], bfr[nxt][p][1], bfr[nxt][p][2], bfr[nxt][p][3],
                               sB + swz(boff[p] + kb + bcol));
                }
#pragma unroll
                for (int mt = 0; mt < 4; mt++)
#pragma unroll
                    for (int nt = 0; nt < 6; nt++) {
                        const int p = nt >> 1, sub = (nt & 1) * 2;
                        asm volatile(
                            "mma.sync.aligned.m16n8k16.row.col.f32.f16.f16.f32 "
                            "{%0,%1,%2,%3}, {%4,%5,%6,%7}, {%8,%9}, {%0,%1,%2,%3};\n"
                            : "+f"(acc[mt][nt][0]), "+f"(acc[mt][nt][1]),
                              "+f"(acc[mt][nt][2]), "+f"(acc[mt][nt][3])
                            : "r"(afr[cur][mt][0]), "r"(afr[cur][mt][1]),
                              "r"(afr[cur][mt][2]), "r"(afr[cur][mt][3]),
                              "r"(bfr[cur][p][sub]), "r"(bfr[cur][p][sub + 1]));
                    }
            }
            nb_sync();
        }

        // ---- Epilogue: half2 logits to scratch + exp partials ----
        float* red = (float*)smem;     // 128 rows x 16 slots
#pragma unroll
        for (int mt = 0; mt < 4; mt++)
#pragma unroll
            for (int i = 0; i < 2; i++) {
                float rp = 0.f;
                const int lr = wm * 64 + mt * 16 + g + 8 * i;
                const size_t rb = (size_t)(m0 + lr) * VPAD;
#pragma unroll
                for (int nt = 0; nt < 6; nt++) {
                    const int gcol = n0 + wn * 48 + nt * 8 + 2 * tig;   // even
                    float l0 = acc[mt][nt][i * 2] * 20.f;
                    float l1 = acc[mt][nt][i * 2 + 1] * 20.f;
                    __stcs((__half2*)(g_scr + rb + gcol), __floats2half2_rn(l0, l1));
                    if (gcol < VCOLS)     rp += __expf(l0 - 20.f);
                    if (gcol + 1 < VCOLS) rp += __expf(l1 - 20.f);
                }
                red[lr * 16 + wn * 4 + tig] = rp;
            }
        nb_sync();
        if (tid < 128) {
            float s = 0.f;
#pragma unroll
            for (int j = 0; j < 16; j++) s += red[tid * 16 + j];
            g_partials[(size_t)nt_tile * MROWS + m0 + tid] = s;
        }
        __threadfence();
        nb_sync();
        if (tid == 0) s_old = atomicAdd(&g_done[mb], 1);
        nb_sync();

        if (s_old == NT2 - 1) {
            __threadfence();
            if (tid < 128) {
                const int row = m0 + tid;
                float s = 0.f;
#pragma unroll 4
                for (int j = 0; j < NT2; j++) s += g_partials[(size_t)j * MROWS + row];
                g_lse[row] = 20.f + logf(s);
            }
            __threadfence();
            nb_sync();
            if (tid == 0) atomicExch(&g_ready[mb], 1);
        }
        nb_sync();
    }
}

extern "C" void kernel_launch(void* const* d_in, const int* in_sizes, int n_in,
                              void* d_out, int out_size) {
    const float* x    = (const float*)d_in[0];  // [2,2048,768]
    const float* wv   = (const float*)d_in[1];  // [50257,768]
    const float* bias = (const float*)d_in[2];  // [50257]
    float* out = (float*)d_out;                 // [2,2048,50257] fp32

    cudaFuncSetAttribute(gemm_kernel, cudaFuncAttributeMaxDynamicSharedMemorySize, DSMEM);

    reset_kernel<<<1, 64>>>();
    norm_rows_kernel<<<(MROWS + VPAD) / 4, 256>>>(x, wv);
    gemm_kernel<<<NCTA, NTHR, DSMEM>>>(out, bias);
}

// round 12
// speedup vs baseline: 1.8897x; 1.8897x over previous
#include <cuda_runtime.h>
#include <cuda_fp16.h>
#include <cstdint>

#define DIMK 768
#define MROWS 4096
#define VCOLS 50257
#define VPAD 50432            // padded vocab = 197 * 256 (even)
#define BM 128
#define BN 256
#define KC 64                 // K elems per stage: 64 half = 128B rows (SW128)
#define NCH (DIMK / KC)       // 12
#define NTILES (VPAD / BN)    // 197
#define NCHUNK 4
#define MB_PER_CHUNK (MROWS / BM / NCHUNK)   // 8 m-blocks per chunk
#define A_STAGE_BYTES (BM * 128)      // 16 KB
#define B_STAGE_BYTES (BN * 128)      // 32 KB
#define STAGE_BYTES (A_STAGE_BYTES + B_STAGE_BYTES)
#define DSMEM (4 * STAGE_BYTES)       // 192 KB

// Scratch (device globals: allocation-free rule)
__device__ __half g_xn[(size_t)MROWS * DIMK];
__device__ __half g_wn[(size_t)VPAD * DIMK];
__device__ __half g_scr[(size_t)MROWS * VPAD];      // fp16 logits scratch
__device__ float g_partials[(size_t)MROWS * NTILES];

__device__ __forceinline__ uint32_t smem_u32(const void* p) {
    uint32_t a;
    asm("{ .reg .u64 t; cvta.to.shared.u64 t, %1; cvt.u32.u64 %0, t; }" : "=r"(a) : "l"(p));
    return a;
}
__device__ __forceinline__ uint32_t swz(uint32_t x) { return x ^ ((x >> 3) & 0x70); }

template <int N>
__device__ __forceinline__ void cpwait() {
    asm volatile("cp.async.wait_group %0;" :: "n"(N) : "memory");
}
__device__ __forceinline__ void cpcommit() {
    asm volatile("cp.async.commit_group;" ::: "memory");
}
__device__ __forceinline__ void cpasync16(uint32_t s, const void* g) {
    asm volatile("cp.async.cg.shared.global [%0], [%1], 16;" :: "r"(s), "l"(g) : "memory");
}
__device__ __forceinline__ void ldm_x4(uint32_t& r0, uint32_t& r1, uint32_t& r2,
                                       uint32_t& r3, uint32_t addr) {
    asm volatile("ldmatrix.sync.aligned.m8n8.x4.shared.b16 {%0,%1,%2,%3}, [%4];"
                 : "=r"(r0), "=r"(r1), "=r"(r2), "=r"(r3) : "r"(addr));
}

// ---------------------------------------------------------------------------
// Row L2-normalize: 4 rows/block, 64 threads/row, single pass, fp16 out.
// ---------------------------------------------------------------------------
__global__ void __launch_bounds__(256) norm_rows_kernel(const float* __restrict__ x,
                                                        const float* __restrict__ wv) {
    const int tid = threadIdx.x;
    const int sub = tid >> 6;
    const int l64 = tid & 63;
    const int row = blockIdx.x * 4 + sub;

    const float* p;
    __half* q;
    bool zero = false;
    if (row < MROWS) {
        p = x + (size_t)row * DIMK;
        q = g_xn + (size_t)row * DIMK;
    } else {
        int r = row - MROWS;
        q = g_wn + (size_t)r * DIMK;
        p = wv + (size_t)r * DIMK;
        zero = (r >= VCOLS);
    }

    float4 v[3];
    float s = 0.f;
    if (!zero) {
#pragma unroll
        for (int j = 0; j < 3; j++) {
            v[j] = *(const float4*)(p + j * 256 + l64 * 4);
            s += v[j].x * v[j].x + v[j].y * v[j].y + v[j].z * v[j].z + v[j].w * v[j].w;
        }
    } else {
#pragma unroll
        for (int j = 0; j < 3; j++) v[j] = make_float4(0.f, 0.f, 0.f, 0.f);
    }
    for (int o = 16; o; o >>= 1) s += __shfl_xor_sync(0xffffffffu, s, o);
    __shared__ float sm[8];
    if ((tid & 31) == 0) sm[tid >> 5] = s;
    __syncthreads();
    const float tot = sm[sub * 2] + sm[sub * 2 + 1];
    const float scale = zero ? 0.f : (1.f / fmaxf(sqrtf(tot), 1e-12f));

#pragma unroll
    for (int j = 0; j < 3; j++) {
        __half2 h0 = __floats2half2_rn(v[j].x * scale, v[j].y * scale);
        __half2 h1 = __floats2half2_rn(v[j].z * scale, v[j].w * scale);
        uint2 pk = make_uint2(*(uint32_t*)&h0, *(uint32_t*)&h1);
        *(uint2*)(q + j * 256 + l64 * 4) = pk;
    }
}

// ---------------------------------------------------------------------------
// fp16 GEMM (r9-proven): m16n8k16 f32.f16.f16.f32 + ldmatrix + 4-stage
// cp.async + frag double-buffering. 128x256 tile / CTA, 256 thr.
// grid = (MB_PER_CHUNK, NTILES); m-block = mb_off + blockIdx.x.
// ---------------------------------------------------------------------------
__global__ void __launch_bounds__(256, 1) gemm_kernel(int mb_off) {
    extern __shared__ __align__(1024) char smem[];

    const int tid = threadIdx.x;
    const int w = tid >> 5, lane = tid & 31;
    const int wm = w >> 2, wn = w & 3;     // 2 x 4 warp grid
    const int m0 = (mb_off + blockIdx.x) * BM;
    const int n0 = blockIdx.y * BN;
    const uint32_t sbase = smem_u32(smem);

    const __half* Ag = g_xn + (size_t)m0 * DIMK;
    const __half* Bg = g_wn + (size_t)n0 * DIMK;

    auto load_chunk = [&](int slot, int k0) {
        uint32_t sA = sbase + slot * STAGE_BYTES;
        uint32_t sB = sA + A_STAGE_BYTES;
#pragma unroll
        for (int i = 0; i < 4; i++) {
            int s = i * 256 + tid;
            int row = s >> 3, seg = s & 7;
            cpasync16(sA + swz(row * 128 + seg * 16),
                      Ag + (size_t)row * DIMK + k0 + seg * 8);
        }
#pragma unroll
        for (int i = 0; i < 8; i++) {
            int s = i * 256 + tid;
            int row = s >> 3, seg = s & 7;
            cpasync16(sB + swz(row * 128 + seg * 16),
                      Bg + (size_t)row * DIMK + k0 + seg * 8);
        }
        cpcommit();
    };

    float acc[4][8][4];
#pragma unroll
    for (int a = 0; a < 4; a++)
#pragma unroll
        for (int b = 0; b < 8; b++)
#pragma unroll
            for (int c = 0; c < 4; c++) acc[a][b][c] = 0.f;

    uint32_t aoff[4], boff[4];
#pragma unroll
    for (int mt = 0; mt < 4; mt++)
        aoff[mt] = (uint32_t)(wm * 64 + mt * 16 + (lane & 15)) * 128;
#pragma unroll
    for (int p = 0; p < 4; p++)
        boff[p] = (uint32_t)(wn * 64 + p * 16 + (lane & 7) + ((lane >> 4) & 1) * 8) * 128;
    const uint32_t acol = ((uint32_t)(lane >> 4)) * 16;
    const uint32_t bcol = ((uint32_t)((lane >> 3) & 1)) * 16;

    uint32_t afr[2][4][4], bfr[2][4][4];

    load_chunk(0, 0);
    load_chunk(1, KC);
    load_chunk(2, 2 * KC);

#pragma unroll 1
    for (int c = 0; c < NCH; c++) {
        if (c + 3 < NCH) load_chunk((c + 3) & 3, (c + 3) * KC);
        if (c <= 8) cpwait<3>();
        else if (c == 9) cpwait<2>();
        else if (c == 10) cpwait<1>();
        else cpwait<0>();
        __syncthreads();

        const uint32_t sA = sbase + (c & 3) * STAGE_BYTES;
        const uint32_t sB = sA + A_STAGE_BYTES;

#pragma unroll
        for (int mt = 0; mt < 4; mt++)
            ldm_x4(afr[0][mt][0], afr[0][mt][1], afr[0][mt][2], afr[0][mt][3],
                   sA + swz(aoff[mt] + acol));
#pragma unroll
        for (int p = 0; p < 4; p++)
            ldm_x4(bfr[0][p][0], bfr[0][p][1], bfr[0][p][2], bfr[0][p][3],
                   sB + swz(boff[p] + bcol));

#pragma unroll
        for (int step = 0; step < KC / 16; step++) {
            const int cur = step & 1;
            if (step < KC / 16 - 1) {
                const int nxt = cur ^ 1;
                const uint32_t kb = (uint32_t)(step + 1) * 32;
#pragma unroll
                for (int mt = 0; mt < 4; mt++)
                    ldm_x4(afr[nxt][mt][0], afr[nxt][mt][1], afr[nxt][mt][2], afr[nxt][mt][3],
                           sA + swz(aoff[mt] + kb + acol));
#pragma unroll
                for (int p = 0; p < 4; p++)
                    ldm_x4(bfr[nxt][p][0], bfr[nxt][p][1], bfr[nxt][p][2], bfr[nxt][p][3],
                           sB + swz(boff[p] + kb + bcol));
            }
#pragma unroll
            for (int mt = 0; mt < 4; mt++)
#pragma unroll
                for (int nt = 0; nt < 8; nt++) {
                    const int p = nt >> 1, sub = (nt & 1) * 2;
                    asm volatile(
                        "mma.sync.aligned.m16n8k16.row.col.f32.f16.f16.f32 "
                        "{%0,%1,%2,%3}, {%4,%5,%6,%7}, {%8,%9}, {%0,%1,%2,%3};\n"
                        : "+f"(acc[mt][nt][0]), "+f"(acc[mt][nt][1]),
                          "+f"(acc[mt][nt][2]), "+f"(acc[mt][nt][3])
                        : "r"(afr[cur][mt][0]), "r"(afr[cur][mt][1]),
                          "r"(afr[cur][mt][2]), "r"(afr[cur][mt][3]),
                          "r"(bfr[cur][p][sub]), "r"(bfr[cur][p][sub + 1]));
                }
        }
        __syncthreads();
    }

    // ---- Epilogue: half2 logits to scratch + exp partials ----
    float* red = (float*)smem;     // 128 rows x 16 slots
    const int g = lane >> 2, tig = lane & 3;
#pragma unroll
    for (int mt = 0; mt < 4; mt++)
#pragma unroll
        for (int i = 0; i < 2; i++) {
            float rp = 0.f;
            const int lr = wm * 64 + mt * 16 + g + 8 * i;
            const size_t rb = (size_t)(m0 + lr) * VPAD;
#pragma unroll
            for (int nt = 0; nt < 8; nt++) {
                const int gcol = n0 + wn * 64 + nt * 8 + 2 * tig;  // even
                float l0 = acc[mt][nt][i * 2] * 20.f;
                float l1 = acc[mt][nt][i * 2 + 1] * 20.f;
                __stcs((__half2*)(g_scr + rb + gcol), __floats2half2_rn(l0, l1));
                if (gcol < VCOLS)     rp += __expf(l0 - 20.f);
                if (gcol + 1 < VCOLS) rp += __expf(l1 - 20.f);
            }
            red[lr * 16 + wn * 4 + tig] = rp;
        }
    __syncthreads();
    if (tid < 128) {
        float s = 0.f;
#pragma unroll
        for (int j = 0; j < 16; j++) s += red[tid * 16 + j];
        g_partials[(size_t)(m0 + tid) * NTILES + blockIdx.y] = s;
    }
}

// ---------------------------------------------------------------------------
// Fixup: ONE ROW per 64-thread block (tiny: co-schedules beside GEMM CTAs).
// Inline LSE reduce over this row's partials, then
// out = scr - lse + bias with alignment-headed float4 stores.
// ---------------------------------------------------------------------------
__global__ void __launch_bounds__(64) fixup_kernel(float* __restrict__ out,
                                                   const float* __restrict__ bias,
                                                   int row_off) {
    const int row = row_off + blockIdx.x;
    const int tid = threadIdx.x;

    float s = 0.f;
    const float* pp = &g_partials[(size_t)row * NTILES];
    for (int j = tid; j < NTILES; j += 64) s += pp[j];
    for (int o = 16; o; o >>= 1) s += __shfl_xor_sync(0xffffffffu, s, o);
    __shared__ float sm[2];
    if ((tid & 31) == 0) sm[tid >> 5] = s;
    __syncthreads();
    const float lse = 20.f + logf(sm[0] + sm[1]);

    const __half* ps = g_scr + (size_t)row * VPAD;
    float* po = out + (size_t)row * VCOLS;

    const int head = (4 - (int)(((uintptr_t)po >> 2) & 3)) & 3;
    if (tid < head)
        po[tid] = __half2float(__ldcs(ps + tid)) - lse + __ldg(bias + tid);
    const int count4 = (VCOLS - head) >> 2;
    const int tail0 = head + count4 * 4;
    if (tid < VCOLS - tail0) {
        const int col = tail0 + tid;
        po[col] = __half2float(__ldcs(ps + col)) - lse + __ldg(bias + col);
    }

    if ((head & 1) == 0) {
#pragma unroll 2
        for (int i = tid; i < count4; i += 64) {
            const int col = head + i * 4;
            float2 a = __half22float2(__ldcs((const __half2*)(ps + col)));
            float2 b = __half22float2(__ldcs((const __half2*)(ps + col + 2)));
            float4 o4;
            o4.x = a.x - lse + __ldg(bias + col);
            o4.y = a.y - lse + __ldg(bias + col + 1);
            o4.z = b.x - lse + __ldg(bias + col + 2);
            o4.w = b.y - lse + __ldg(bias + col + 3);
            *(float4*)(po + col) = o4;
        }
    } else {
#pragma unroll 2
        for (int i = tid; i < count4; i += 64) {
            const int col = head + i * 4;
            float4 o4;
            o4.x = __half2float(__ldcs(ps + col))     - lse + __ldg(bias + col);
            o4.y = __half2float(__ldcs(ps + col + 1)) - lse + __ldg(bias + col + 1);
            o4.z = __half2float(__ldcs(ps + col + 2)) - lse + __ldg(bias + col + 2);
            o4.w = __half2float(__ldcs(ps + col + 3)) - lse + __ldg(bias + col + 3);
            *(float4*)(po + col) = o4;
        }
    }
}

extern "C" void kernel_launch(void* const* d_in, const int* in_sizes, int n_in,
                              void* d_out, int out_size) {
    const float* x    = (const float*)d_in[0];  // [2,2048,768]
    const float* wv   = (const float*)d_in[1];  // [50257,768]
    const float* bias = (const float*)d_in[2];  // [50257]
    float* out = (float*)d_out;                 // [2,2048,50257] fp32

    // One-time host-object setup (streams/events: no device memory involved).
    static cudaStream_t s2 = nullptr;
    static cudaEvent_t evG[NCHUNK], evF;
    if (s2 == nullptr) {
        cudaStreamCreateWithFlags(&s2, cudaStreamNonBlocking);
        for (int i = 0; i < NCHUNK; i++)
            cudaEventCreateWithFlags(&evG[i], cudaEventDisableTiming);
        cudaEventCreateWithFlags(&evF, cudaEventDisableTiming);
        cudaFuncSetAttribute(gemm_kernel, cudaFuncAttributeMaxDynamicSharedMemorySize, DSMEM);
    }

    norm_rows_kernel<<<(MROWS + VPAD) / 4, 256>>>(x, wv);

    for (int c = 0; c < NCHUNK; c++) {
        gemm_kernel<<<dim3(MB_PER_CHUNK, NTILES), 256, DSMEM>>>(c * MB_PER_CHUNK);
        cudaEventRecord(evG[c], 0);
        cudaStreamWaitEvent(s2, evG[c], 0);
        fixup_kernel<<<MB_PER_CHUNK * BM, 64, 0, s2>>>(out, bias,
                                                       c * MB_PER_CHUNK * BM);
    }
    cudaEventRecord(evF, s2);
    cudaStreamWaitEvent(0, evF, 0);
}

// round 13
// speedup vs baseline: 2.2936x; 1.2137x over previous
#include <cuda_runtime.h>
#include <cuda_fp16.h>
#include <cstdint>

#define DIMK 768
#define MROWS 4096
#define VCOLS 50257
#define VPAD 50432            // padded vocab = 197 * 256 (even)
#define BM 128
#define BN 256
#define KC 64                 // K elems per stage: 64 half = 128B rows (SW128)
#define NCH (DIMK / KC)       // 12
#define NTILES (VPAD / BN)    // 197
#define A_STAGE_BYTES (BM * 128)      // 16 KB
#define B_STAGE_BYTES (BN * 128)      // 32 KB
#define STAGE_BYTES (A_STAGE_BYTES + B_STAGE_BYTES)
#define DSMEM (4 * STAGE_BYTES)       // 192 KB

// Scratch (device globals: allocation-free rule)
__device__ __half g_xn[(size_t)MROWS * DIMK];
__device__ __half g_wn[(size_t)VPAD * DIMK];
__device__ __half g_scr[(size_t)MROWS * VPAD];      // fp16 logits scratch
__device__ float g_partials[(size_t)MROWS * NTILES];

__device__ __forceinline__ uint32_t smem_u32(const void* p) {
    uint32_t a;
    asm("{ .reg .u64 t; cvta.to.shared.u64 t, %1; cvt.u32.u64 %0, t; }" : "=r"(a) : "l"(p));
    return a;
}
__device__ __forceinline__ uint32_t swz(uint32_t x) { return x ^ ((x >> 3) & 0x70); }

template <int N>
__device__ __forceinline__ void cpwait() {
    asm volatile("cp.async.wait_group %0;" :: "n"(N) : "memory");
}
__device__ __forceinline__ void cpcommit() {
    asm volatile("cp.async.commit_group;" ::: "memory");
}
__device__ __forceinline__ void cpasync16(uint32_t s, const void* g) {
    asm volatile("cp.async.cg.shared.global [%0], [%1], 16;" :: "r"(s), "l"(g) : "memory");
}
__device__ __forceinline__ void ldm_x4(uint32_t& r0, uint32_t& r1, uint32_t& r2,
                                       uint32_t& r3, uint32_t addr) {
    asm volatile("ldmatrix.sync.aligned.m8n8.x4.shared.b16 {%0,%1,%2,%3}, [%4];"
                 : "=r"(r0), "=r"(r1), "=r"(r2), "=r"(r3) : "r"(addr));
}

// ---------------------------------------------------------------------------
// Row L2-normalize: 4 rows/block, 64 threads/row, single pass, fp16 out.
// ---------------------------------------------------------------------------
__global__ void __launch_bounds__(256) norm_rows_kernel(const float* __restrict__ x,
                                                        const float* __restrict__ wv) {
    const int tid = threadIdx.x;
    const int sub = tid >> 6;
    const int l64 = tid & 63;
    const int row = blockIdx.x * 4 + sub;

    const float* p;
    __half* q;
    bool zero = false;
    if (row < MROWS) {
        p = x + (size_t)row * DIMK;
        q = g_xn + (size_t)row * DIMK;
    } else {
        int r = row - MROWS;
        q = g_wn + (size_t)r * DIMK;
        p = wv + (size_t)r * DIMK;
        zero = (r >= VCOLS);
    }

    float4 v[3];
    float s = 0.f;
    if (!zero) {
#pragma unroll
        for (int j = 0; j < 3; j++) {
            v[j] = *(const float4*)(p + j * 256 + l64 * 4);
            s += v[j].x * v[j].x + v[j].y * v[j].y + v[j].z * v[j].z + v[j].w * v[j].w;
        }
    } else {
#pragma unroll
        for (int j = 0; j < 3; j++) v[j] = make_float4(0.f, 0.f, 0.f, 0.f);
    }
    for (int o = 16; o; o >>= 1) s += __shfl_xor_sync(0xffffffffu, s, o);
    __shared__ float sm[8];
    if ((tid & 31) == 0) sm[tid >> 5] = s;
    __syncthreads();
    const float tot = sm[sub * 2] + sm[sub * 2 + 1];
    const float scale = zero ? 0.f : (1.f / fmaxf(sqrtf(tot), 1e-12f));

#pragma unroll
    for (int j = 0; j < 3; j++) {
        __half2 h0 = __floats2half2_rn(v[j].x * scale, v[j].y * scale);
        __half2 h1 = __floats2half2_rn(v[j].z * scale, v[j].w * scale);
        uint2 pk = make_uint2(*(uint32_t*)&h0, *(uint32_t*)&h1);
        *(uint2*)(q + j * 256 + l64 * 4) = pk;
    }
}

// ---------------------------------------------------------------------------
// fp16 GEMM (r9-proven): m16n8k16 f32.f16.f16.f32 + ldmatrix + 4-stage
// cp.async + register-level fragment double-buffering. 128x256 tile / CTA.
// Epilogue: half2 logits -> g_scr (evict-first), exp partials -> g_partials.
// ---------------------------------------------------------------------------
__global__ void __launch_bounds__(256, 1) gemm_kernel() {
    extern __shared__ __align__(1024) char smem[];

    const int tid = threadIdx.x;
    const int w = tid >> 5, lane = tid & 31;
    const int wm = w >> 2, wn = w & 3;     // 2 x 4 warp grid
    const int m0 = blockIdx.x * BM;        // m fastest: L2-friendly waves
    const int n0 = blockIdx.y * BN;
    const uint32_t sbase = smem_u32(smem);

    const __half* Ag = g_xn + (size_t)m0 * DIMK;
    const __half* Bg = g_wn + (size_t)n0 * DIMK;

    auto load_chunk = [&](int slot, int k0) {
        uint32_t sA = sbase + slot * STAGE_BYTES;
        uint32_t sB = sA + A_STAGE_BYTES;
#pragma unroll
        for (int i = 0; i < 4; i++) {
            int s = i * 256 + tid;
            int row = s >> 3, seg = s & 7;
            cpasync16(sA + swz(row * 128 + seg * 16),
                      Ag + (size_t)row * DIMK + k0 + seg * 8);
        }
#pragma unroll
        for (int i = 0; i < 8; i++) {
            int s = i * 256 + tid;
            int row = s >> 3, seg = s & 7;
            cpasync16(sB + swz(row * 128 + seg * 16),
                      Bg + (size_t)row * DIMK + k0 + seg * 8);
        }
        cpcommit();
    };

    float acc[4][8][4];
#pragma unroll
    for (int a = 0; a < 4; a++)
#pragma unroll
        for (int b = 0; b < 8; b++)
#pragma unroll
            for (int c = 0; c < 4; c++) acc[a][b][c] = 0.f;

    uint32_t aoff[4], boff[4];
#pragma unroll
    for (int mt = 0; mt < 4; mt++)
        aoff[mt] = (uint32_t)(wm * 64 + mt * 16 + (lane & 15)) * 128;
#pragma unroll
    for (int p = 0; p < 4; p++)
        boff[p] = (uint32_t)(wn * 64 + p * 16 + (lane & 7) + ((lane >> 4) & 1) * 8) * 128;
    const uint32_t acol = ((uint32_t)(lane >> 4)) * 16;
    const uint32_t bcol = ((uint32_t)((lane >> 3) & 1)) * 16;

    uint32_t afr[2][4][4], bfr[2][4][4];

    load_chunk(0, 0);
    load_chunk(1, KC);
    load_chunk(2, 2 * KC);

#pragma unroll 1
    for (int c = 0; c < NCH; c++) {
        if (c + 3 < NCH) load_chunk((c + 3) & 3, (c + 3) * KC);
        if (c <= 8) cpwait<3>();
        else if (c == 9) cpwait<2>();
        else if (c == 10) cpwait<1>();
        else cpwait<0>();
        __syncthreads();

        const uint32_t sA = sbase + (c & 3) * STAGE_BYTES;
        const uint32_t sB = sA + A_STAGE_BYTES;

#pragma unroll
        for (int mt = 0; mt < 4; mt++)
            ldm_x4(afr[0][mt][0], afr[0][mt][1], afr[0][mt][2], afr[0][mt][3],
                   sA + swz(aoff[mt] + acol));
#pragma unroll
        for (int p = 0; p < 4; p++)
            ldm_x4(bfr[0][p][0], bfr[0][p][1], bfr[0][p][2], bfr[0][p][3],
                   sB + swz(boff[p] + bcol));

#pragma unroll
        for (int step = 0; step < KC / 16; step++) {
            const int cur = step & 1;
            if (step < KC / 16 - 1) {
                const int nxt = cur ^ 1;
                const uint32_t kb = (uint32_t)(step + 1) * 32;
#pragma unroll
                for (int mt = 0; mt < 4; mt++)
                    ldm_x4(afr[nxt][mt][0], afr[nxt][mt][1], afr[nxt][mt][2], afr[nxt][mt][3],
                           sA + swz(aoff[mt] + kb + acol));
#pragma unroll
                for (int p = 0; p < 4; p++)
                    ldm_x4(bfr[nxt][p][0], bfr[nxt][p][1], bfr[nxt][p][2], bfr[nxt][p][3],
                           sB + swz(boff[p] + kb + bcol));
            }
#pragma unroll
            for (int mt = 0; mt < 4; mt++)
#pragma unroll
                for (int nt = 0; nt < 8; nt++) {
                    const int p = nt >> 1, sub = (nt & 1) * 2;
                    asm volatile(
                        "mma.sync.aligned.m16n8k16.row.col.f32.f16.f16.f32 "
                        "{%0,%1,%2,%3}, {%4,%5,%6,%7}, {%8,%9}, {%0,%1,%2,%3};\n"
                        : "+f"(acc[mt][nt][0]), "+f"(acc[mt][nt][1]),
                          "+f"(acc[mt][nt][2]), "+f"(acc[mt][nt][3])
                        : "r"(afr[cur][mt][0]), "r"(afr[cur][mt][1]),
                          "r"(afr[cur][mt][2]), "r"(afr[cur][mt][3]),
                          "r"(bfr[cur][p][sub]), "r"(bfr[cur][p][sub + 1]));
                }
        }
        __syncthreads();
    }

    // ---- Epilogue: half2 logits to scratch + exp partials ----
    float* red = (float*)smem;     // 128 rows x 16 slots
    const int g = lane >> 2, tig = lane & 3;
#pragma unroll
    for (int mt = 0; mt < 4; mt++)
#pragma unroll
        for (int i = 0; i < 2; i++) {
            float rp = 0.f;
            const int lr = wm * 64 + mt * 16 + g + 8 * i;
            const size_t rb = (size_t)(m0 + lr) * VPAD;
#pragma unroll
            for (int nt = 0; nt < 8; nt++) {
                const int gcol = n0 + wn * 64 + nt * 8 + 2 * tig;  // even
                float l0 = acc[mt][nt][i * 2] * 20.f;
                float l1 = acc[mt][nt][i * 2 + 1] * 20.f;
                __stcs((__half2*)(g_scr + rb + gcol), __floats2half2_rn(l0, l1));
                if (gcol < VCOLS)     rp += __expf(l0 - 20.f);
                if (gcol + 1 < VCOLS) rp += __expf(l1 - 20.f);
            }
            red[lr * 16 + wn * 4 + tig] = rp;
        }
    __syncthreads();
    if (tid < 128) {
        float s = 0.f;
#pragma unroll
        for (int j = 0; j < 16; j++) s += red[tid * 16 + j];
        g_partials[(size_t)(m0 + tid) * NTILES + blockIdx.y] = s;
    }
}

// ---------------------------------------------------------------------------
// Fixup: HALF a row per 256-thread block (grid 2 x 4096). Redundant per-block
// LSE reduce (cheap), then out = scr - lse + bias, float4 stores.
// ---------------------------------------------------------------------------
__global__ void __launch_bounds__(256) fixup_kernel(float* __restrict__ out,
                                                    const float* __restrict__ bias) {
    const int row = blockIdx.y;
    const int tid = threadIdx.x;

    // LSE = 20 + log(sum partials)  (computed by both half-blocks)
    float s = 0.f;
    const float* pp = &g_partials[(size_t)row * NTILES];
    for (int j = tid; j < NTILES; j += 256) s += pp[j];
    for (int o = 16; o; o >>= 1) s += __shfl_xor_sync(0xffffffffu, s, o);
    __shared__ float sm[8];
    if ((tid & 31) == 0) sm[tid >> 5] = s;
    __syncthreads();
    if (tid < 8) {
        float t = sm[tid];
        for (int o = 4; o; o >>= 1) t += __shfl_xor_sync(0xffu, t, o);
        if (tid == 0) sm[0] = 20.f + logf(t);
    }
    __syncthreads();
    const float lse = sm[0];

    // Column range for this half (25128 is a multiple of 4: alignment logic
    // relative to the row base carries over unchanged).
    const int c0 = blockIdx.x ? (VCOLS / 2) : 0;
    const int c1 = blockIdx.x ? VCOLS : (VCOLS / 2);

    const __half* ps = g_scr + (size_t)row * VPAD;
    float* po = out + (size_t)row * VCOLS;

    // head: scalar cols until po+c0+head is 16B aligned
    const int head = (4 - (int)(((uintptr_t)(po + c0) >> 2) & 3)) & 3;
    if (tid < head && c0 + tid < c1) {
        const int col = c0 + tid;
        po[col] = __half2float(__ldcs(ps + col)) - lse + __ldg(bias + col);
    }
    const int count4 = (c1 - c0 - head) >> 2;
    const int tail0 = c0 + head + count4 * 4;
    if (tid < c1 - tail0) {
        const int col = tail0 + tid;
        po[col] = __half2float(__ldcs(ps + col)) - lse + __ldg(bias + col);
    }

    const int colbase = c0 + head;
    if ((colbase & 1) == 0) {
        // scratch cols even: half2 loads
#pragma unroll 2
        for (int i = tid; i < count4; i += 256) {
            const int col = colbase + i * 4;
            float2 a = __half22float2(__ldcs((const __half2*)(ps + col)));
            float2 b = __half22float2(__ldcs((const __half2*)(ps + col + 2)));
            float4 o4;
            o4.x = a.x - lse + __ldg(bias + col);
            o4.y = a.y - lse + __ldg(bias + col + 1);
            o4.z = b.x - lse + __ldg(bias + col + 2);
            o4.w = b.y - lse + __ldg(bias + col + 3);
            *(float4*)(po + col) = o4;
        }
    } else {
        // odd base: scalar half loads, vector store
#pragma unroll 2
        for (int i = tid; i < count4; i += 256) {
            const int col = colbase + i * 4;
            float4 o4;
            o4.x = __half2float(__ldcs(ps + col))     - lse + __ldg(bias + col);
            o4.y = __half2float(__ldcs(ps + col + 1)) - lse + __ldg(bias + col + 1);
            o4.z = __half2float(__ldcs(ps + col + 2)) - lse + __ldg(bias + col + 2);
            o4.w = __half2float(__ldcs(ps + col + 3)) - lse + __ldg(bias + col + 3);
            *(float4*)(po + col) = o4;
        }
    }
}

extern "C" void kernel_launch(void* const* d_in, const int* in_sizes, int n_in,
                              void* d_out, int out_size) {
    const float* x    = (const float*)d_in[0];  // [2,2048,768]
    const float* wv   = (const float*)d_in[1];  // [50257,768]
    const float* bias = (const float*)d_in[2];  // [50257]
    float* out = (float*)d_out;                 // [2,2048,50257] fp32

    cudaFuncSetAttribute(gemm_kernel, cudaFuncAttributeMaxDynamicSharedMemorySize, DSMEM);

    norm_rows_kernel<<<(MROWS + VPAD) / 4, 256>>>(x, wv);
    gemm_kernel<<<dim3(MROWS / BM, NTILES), 256, DSMEM>>>();
    fixup_kernel<<<dim3(2, MROWS), 256>>>(out, bias);
}

// round 14
// speedup vs baseline: 2.3108x; 1.0075x over previous
#include <cuda_runtime.h>
#include <cuda_fp16.h>
#include <cstdint>

#define DIMK 768
#define MROWS 4096
#define VCOLS 50257
#define VPAD 50432            // padded vocab = 197 * 256 (even)
#define BM 128
#define BN 256
#define KC 64                 // K elems per stage: 64 half = 128B rows (SW128)
#define NCH (DIMK / KC)       // 12
#define NTILES (VPAD / BN)    // 197
#define A_STAGE_BYTES (BM * 128)      // 16 KB
#define B_STAGE_BYTES (BN * 128)      // 32 KB
#define STAGE_BYTES (A_STAGE_BYTES + B_STAGE_BYTES)
#define DSMEM (4 * STAGE_BYTES)       // 192 KB

// Scratch (device globals: allocation-free rule)
__device__ __half g_xn[(size_t)MROWS * DIMK];
__device__ __half g_wn[(size_t)VPAD * DIMK];
__device__ __half g_scr[(size_t)MROWS * VPAD];      // fp16 logits scratch
__device__ float g_partials[(size_t)MROWS * NTILES];
__device__ float g_lse[MROWS];

__device__ __forceinline__ uint32_t smem_u32(const void* p) {
    uint32_t a;
    asm("{ .reg .u64 t; cvta.to.shared.u64 t, %1; cvt.u32.u64 %0, t; }" : "=r"(a) : "l"(p));
    return a;
}
__device__ __forceinline__ uint32_t swz(uint32_t x) { return x ^ ((x >> 3) & 0x70); }

template <int N>
__device__ __forceinline__ void cpwait() {
    asm volatile("cp.async.wait_group %0;" :: "n"(N) : "memory");
}
__device__ __forceinline__ void cpcommit() {
    asm volatile("cp.async.commit_group;" ::: "memory");
}
__device__ __forceinline__ void cpasync16(uint32_t s, const void* g) {
    asm volatile("cp.async.cg.shared.global [%0], [%1], 16;" :: "r"(s), "l"(g) : "memory");
}
__device__ __forceinline__ void ldm_x4(uint32_t& r0, uint32_t& r1, uint32_t& r2,
                                       uint32_t& r3, uint32_t addr) {
    asm volatile("ldmatrix.sync.aligned.m8n8.x4.shared.b16 {%0,%1,%2,%3}, [%4];"
                 : "=r"(r0), "=r"(r1), "=r"(r2), "=r"(r3) : "r"(addr));
}

// ---------------------------------------------------------------------------
// Row L2-normalize: 4 rows/block, 64 threads/row, single pass, fp16 out.
// ---------------------------------------------------------------------------
__global__ void __launch_bounds__(256) norm_rows_kernel(const float* __restrict__ x,
                                                        const float* __restrict__ wv) {
    const int tid = threadIdx.x;
    const int sub = tid >> 6;
    const int l64 = tid & 63;
    const int row = blockIdx.x * 4 + sub;

    const float* p;
    __half* q;
    bool zero = false;
    if (row < MROWS) {
        p = x + (size_t)row * DIMK;
        q = g_xn + (size_t)row * DIMK;
    } else {
        int r = row - MROWS;
        q = g_wn + (size_t)r * DIMK;
        p = wv + (size_t)r * DIMK;
        zero = (r >= VCOLS);
    }

    float4 v[3];
    float s = 0.f;
    if (!zero) {
#pragma unroll
        for (int j = 0; j < 3; j++) {
            v[j] = *(const float4*)(p + j * 256 + l64 * 4);
            s += v[j].x * v[j].x + v[j].y * v[j].y + v[j].z * v[j].z + v[j].w * v[j].w;
        }
    } else {
#pragma unroll
        for (int j = 0; j < 3; j++) v[j] = make_float4(0.f, 0.f, 0.f, 0.f);
    }
    for (int o = 16; o; o >>= 1) s += __shfl_xor_sync(0xffffffffu, s, o);
    __shared__ float sm[8];
    if ((tid & 31) == 0) sm[tid >> 5] = s;
    __syncthreads();
    const float tot = sm[sub * 2] + sm[sub * 2 + 1];
    const float scale = zero ? 0.f : (1.f / fmaxf(sqrtf(tot), 1e-12f));

#pragma unroll
    for (int j = 0; j < 3; j++) {
        __half2 h0 = __floats2half2_rn(v[j].x * scale, v[j].y * scale);
        __half2 h1 = __floats2half2_rn(v[j].z * scale, v[j].w * scale);
        uint2 pk = make_uint2(*(uint32_t*)&h0, *(uint32_t*)&h1);
        *(uint2*)(q + j * 256 + l64 * 4) = pk;
    }
}

// ---------------------------------------------------------------------------
// fp16 GEMM (r9-proven): m16n8k16 f32.f16.f16.f32 + ldmatrix + 4-stage
// cp.async + register-level fragment double-buffering. 128x256 tile / CTA.
// Epilogue: half2 logits -> g_scr (default policy: tail may stay in L2 for
// the fixup pass), exp partials -> g_partials.
// ---------------------------------------------------------------------------
__global__ void __launch_bounds__(256, 1) gemm_kernel() {
    extern __shared__ __align__(1024) char smem[];

    const int tid = threadIdx.x;
    const int w = tid >> 5, lane = tid & 31;
    const int wm = w >> 2, wn = w & 3;     // 2 x 4 warp grid
    const int m0 = blockIdx.x * BM;        // m fastest: L2-friendly waves
    const int n0 = blockIdx.y * BN;
    const uint32_t sbase = smem_u32(smem);

    const __half* Ag = g_xn + (size_t)m0 * DIMK;
    const __half* Bg = g_wn + (size_t)n0 * DIMK;

    auto load_chunk = [&](int slot, int k0) {
        uint32_t sA = sbase + slot * STAGE_BYTES;
        uint32_t sB = sA + A_STAGE_BYTES;
#pragma unroll
        for (int i = 0; i < 4; i++) {
            int s = i * 256 + tid;
            int row = s >> 3, seg = s & 7;
            cpasync16(sA + swz(row * 128 + seg * 16),
                      Ag + (size_t)row * DIMK + k0 + seg * 8);
        }
#pragma unroll
        for (int i = 0; i < 8; i++) {
            int s = i * 256 + tid;
            int row = s >> 3, seg = s & 7;
            cpasync16(sB + swz(row * 128 + seg * 16),
                      Bg + (size_t)row * DIMK + k0 + seg * 8);
        }
        cpcommit();
    };

    float acc[4][8][4];
#pragma unroll
    for (int a = 0; a < 4; a++)
#pragma unroll
        for (int b = 0; b < 8; b++)
#pragma unroll
            for (int c = 0; c < 4; c++) acc[a][b][c] = 0.f;

    uint32_t aoff[4], boff[4];
#pragma unroll
    for (int mt = 0; mt < 4; mt++)
        aoff[mt] = (uint32_t)(wm * 64 + mt * 16 + (lane & 15)) * 128;
#pragma unroll
    for (int p = 0; p < 4; p++)
        boff[p] = (uint32_t)(wn * 64 + p * 16 + (lane & 7) + ((lane >> 4) & 1) * 8) * 128;
    const uint32_t acol = ((uint32_t)(lane >> 4)) * 16;
    const uint32_t bcol = ((uint32_t)((lane >> 3) & 1)) * 16;

    uint32_t afr[2][4][4], bfr[2][4][4];

    load_chunk(0, 0);
    load_chunk(1, KC);
    load_chunk(2, 2 * KC);

#pragma unroll 1
    for (int c = 0; c < NCH; c++) {
        if (c + 3 < NCH) load_chunk((c + 3) & 3, (c + 3) * KC);
        if (c <= 8) cpwait<3>();
        else if (c == 9) cpwait<2>();
        else if (c == 10) cpwait<1>();
        else cpwait<0>();
        __syncthreads();

        const uint32_t sA = sbase + (c & 3) * STAGE_BYTES;
        const uint32_t sB = sA + A_STAGE_BYTES;

#pragma unroll
        for (int mt = 0; mt < 4; mt++)
            ldm_x4(afr[0][mt][0], afr[0][mt][1], afr[0][mt][2], afr[0][mt][3],
                   sA + swz(aoff[mt] + acol));
#pragma unroll
        for (int p = 0; p < 4; p++)
            ldm_x4(bfr[0][p][0], bfr[0][p][1], bfr[0][p][2], bfr[0][p][3],
                   sB + swz(boff[p] + bcol));

#pragma unroll
        for (int step = 0; step < KC / 16; step++) {
            const int cur = step & 1;
            if (step < KC / 16 - 1) {
                const int nxt = cur ^ 1;
                const uint32_t kb = (uint32_t)(step + 1) * 32;
#pragma unroll
                for (int mt = 0; mt < 4; mt++)
                    ldm_x4(afr[nxt][mt][0], afr[nxt][mt][1], afr[nxt][mt][2], afr[nxt][mt][3],
                           sA + swz(aoff[mt] + kb + acol));
#pragma unroll
                for (int p = 0; p < 4; p++)
                    ldm_x4(bfr[nxt][p][0], bfr[nxt][p][1], bfr[nxt][p][2], bfr[nxt][p][3],
                           sB + swz(boff[p] + kb + bcol));
            }
#pragma unroll
            for (int mt = 0; mt < 4; mt++)
#pragma unroll
                for (int nt = 0; nt < 8; nt++) {
                    const int p = nt >> 1, sub = (nt & 1) * 2;
                    asm volatile(
                        "mma.sync.aligned.m16n8k16.row.col.f32.f16.f16.f32 "
                        "{%0,%1,%2,%3}, {%4,%5,%6,%7}, {%8,%9}, {%0,%1,%2,%3};\n"
                        : "+f"(acc[mt][nt][0]), "+f"(acc[mt][nt][1]),
                          "+f"(acc[mt][nt][2]), "+f"(acc[mt][nt][3])
                        : "r"(afr[cur][mt][0]), "r"(afr[cur][mt][1]),
                          "r"(afr[cur][mt][2]), "r"(afr[cur][mt][3]),
                          "r"(bfr[cur][p][sub]), "r"(bfr[cur][p][sub + 1]));
                }
        }
        __syncthreads();
    }

    // ---- Epilogue: half2 logits to scratch + exp partials ----
    float* red = (float*)smem;     // 128 rows x 16 slots
    const int g = lane >> 2, tig = lane & 3;
#pragma unroll
    for (int mt = 0; mt < 4; mt++)
#pragma unroll
        for (int i = 0; i < 2; i++) {
            float rp = 0.f;
            const int lr = wm * 64 + mt * 16 + g + 8 * i;
            const size_t rb = (size_t)(m0 + lr) * VPAD;
#pragma unroll
            for (int nt = 0; nt < 8; nt++) {
                const int gcol = n0 + wn * 64 + nt * 8 + 2 * tig;  // even
                float l0 = acc[mt][nt][i * 2] * 20.f;
                float l1 = acc[mt][nt][i * 2 + 1] * 20.f;
                *(__half2*)(g_scr + rb + gcol) = __floats2half2_rn(l0, l1);
                if (gcol < VCOLS)     rp += __expf(l0 - 20.f);
                if (gcol + 1 < VCOLS) rp += __expf(l1 - 20.f);
            }
            red[lr * 16 + wn * 4 + tig] = rp;
        }
    __syncthreads();
    if (tid < 128) {
        float s = 0.f;
#pragma unroll
        for (int j = 0; j < 16; j++) s += red[tid * 16 + j];
        g_partials[(size_t)(m0 + tid) * NTILES + blockIdx.y] = s;
    }
}

// ---------------------------------------------------------------------------
// Per-row logsumexp: lse = 20 + log(sum of partials). Deterministic. ~7us.
// ---------------------------------------------------------------------------
__global__ void __launch_bounds__(128) lse_kernel() {
    int row = blockIdx.x;
    float s = 0.f;
    for (int j = threadIdx.x; j < NTILES; j += 128)
        s += g_partials[(size_t)row * NTILES + j];
    for (int o = 16; o; o >>= 1) s += __shfl_xor_sync(0xffffffffu, s, o);
    __shared__ float sm[4];
    if ((threadIdx.x & 31) == 0) sm[threadIdx.x >> 5] = s;
    __syncthreads();
    if (threadIdx.x == 0)
        g_lse[row] = 20.f + logf(sm[0] + sm[1] + sm[2] + sm[3]);
}

// ---------------------------------------------------------------------------
// Fixup: one row per 512-thread block, lse precomputed. Pure stream:
// out = scr - lse + bias with alignment-headed float4 stores.
// ---------------------------------------------------------------------------
__global__ void __launch_bounds__(512) fixup_kernel(float* __restrict__ out,
                                                    const float* __restrict__ bias) {
    const int row = blockIdx.x;
    const int tid = threadIdx.x;
    const float lse = g_lse[row];

    const __half* ps = g_scr + (size_t)row * VPAD;
    float* po = out + (size_t)row * VCOLS;

    // head: scalar cols until po+head is 16B aligned
    const int head = (4 - (int)(((uintptr_t)po >> 2) & 3)) & 3;
    if (tid < head)
        po[tid] = __half2float(__ldcs(ps + tid)) - lse + __ldg(bias + tid);
    const int count4 = (VCOLS - head) >> 2;
    const int tail0 = head + count4 * 4;
    if (tid < VCOLS - tail0) {
        const int col = tail0 + tid;
        po[col] = __half2float(__ldcs(ps + col)) - lse + __ldg(bias + col);
    }

    if ((head & 1) == 0) {
        // scratch cols even: half2 loads
#pragma unroll 2
        for (int i = tid; i < count4; i += 512) {
            const int col = head + i * 4;
            float2 a = __half22float2(__ldcs((const __half2*)(ps + col)));
            float2 b = __half22float2(__ldcs((const __half2*)(ps + col + 2)));
            float4 o4;
            o4.x = a.x - lse + __ldg(bias + col);
            o4.y = a.y - lse + __ldg(bias + col + 1);
            o4.z = b.x - lse + __ldg(bias + col + 2);
            o4.w = b.y - lse + __ldg(bias + col + 3);
            *(float4*)(po + col) = o4;
        }
    } else {
        // odd head: scalar half loads, vector store
#pragma unroll 2
        for (int i = tid; i < count4; i += 512) {
            const int col = head + i * 4;
            float4 o4;
            o4.x = __half2float(__ldcs(ps + col))     - lse + __ldg(bias + col);
            o4.y = __half2float(__ldcs(ps + col + 1)) - lse + __ldg(bias + col + 1);
            o4.z = __half2float(__ldcs(ps + col + 2)) - lse + __ldg(bias + col + 2);
            o4.w = __half2float(__ldcs(ps + col + 3)) - lse + __ldg(bias + col + 3);
            *(float4*)(po + col) = o4;
        }
    }
}

extern "C" void kernel_launch(void* const* d_in, const int* in_sizes, int n_in,
                              void* d_out, int out_size) {
    const float* x    = (const float*)d_in[0];  // [2,2048,768]
    const float* wv   = (const float*)d_in[1];  // [50257,768]
    const float* bias = (const float*)d_in[2];  // [50257]
    float* out = (float*)d_out;                 // [2,2048,50257] fp32

    cudaFuncSetAttribute(gemm_kernel, cudaFuncAttributeMaxDynamicSharedMemorySize, DSMEM);

    norm_rows_kernel<<<(MROWS + VPAD) / 4, 256>>>(x, wv);
    gemm_kernel<<<dim3(MROWS / BM, NTILES), 256, DSMEM>>>();
    lse_kernel<<<MROWS, 128>>>();
    fixup_kernel<<<MROWS, 512>>>(out, bias);
}

// round 15
// speedup vs baseline: 2.3193x; 1.0037x over previous
#include <cuda_runtime.h>
#include <cuda_fp16.h>
#include <cstdint>

#define DIMK 768
#define MROWS 4096
#define VCOLS 50257
#define VPAD 50432            // padded vocab = 197 * 256 (even)
#define BM 128
#define BN 256
#define KC 64                 // K elems per stage: 64 half = 128B rows (SW128)
#define NCH (DIMK / KC)       // 12
#define NTILES (VPAD / BN)    // 197
#define A_STAGE_BYTES (BM * 128)      // 16 KB
#define B_STAGE_BYTES (BN * 128)      // 32 KB
#define STAGE_BYTES (A_STAGE_BYTES + B_STAGE_BYTES)
#define DSMEM (4 * STAGE_BYTES)       // 192 KB

// Scratch (device globals: allocation-free rule)
__device__ __half g_xn[(size_t)MROWS * DIMK];
__device__ __half g_wn[(size_t)VPAD * DIMK];
__device__ __half g_scr[(size_t)MROWS * VPAD];      // fp16 logits scratch
__device__ float g_partials[(size_t)MROWS * NTILES];
__device__ float g_lse[MROWS];

__device__ __forceinline__ uint32_t smem_u32(const void* p) {
    uint32_t a;
    asm("{ .reg .u64 t; cvta.to.shared.u64 t, %1; cvt.u32.u64 %0, t; }" : "=r"(a) : "l"(p));
    return a;
}
__device__ __forceinline__ uint32_t swz(uint32_t x) { return x ^ ((x >> 3) & 0x70); }

template <int N>
__device__ __forceinline__ void cpwait() {
    asm volatile("cp.async.wait_group %0;" :: "n"(N) : "memory");
}
__device__ __forceinline__ void cpcommit() {
    asm volatile("cp.async.commit_group;" ::: "memory");
}
__device__ __forceinline__ void cpasync16(uint32_t s, const void* g) {
    asm volatile("cp.async.cg.shared.global [%0], [%1], 16;" :: "r"(s), "l"(g) : "memory");
}
__device__ __forceinline__ void ldm_x4(uint32_t& r0, uint32_t& r1, uint32_t& r2,
                                       uint32_t& r3, uint32_t addr) {
    asm volatile("ldmatrix.sync.aligned.m8n8.x4.shared.b16 {%0,%1,%2,%3}, [%4];"
                 : "=r"(r0), "=r"(r1), "=r"(r2), "=r"(r3) : "r"(addr));
}

// ---------------------------------------------------------------------------
// Row L2-normalize: 4 rows/block, 64 threads/row, single pass, fp16 out.
// ---------------------------------------------------------------------------
__global__ void __launch_bounds__(256) norm_rows_kernel(const float* __restrict__ x,
                                                        const float* __restrict__ wv) {
    const int tid = threadIdx.x;
    const int sub = tid >> 6;
    const int l64 = tid & 63;
    const int row = blockIdx.x * 4 + sub;

    const float* p;
    __half* q;
    bool zero = false;
    if (row < MROWS) {
        p = x + (size_t)row * DIMK;
        q = g_xn + (size_t)row * DIMK;
    } else {
        int r = row - MROWS;
        q = g_wn + (size_t)r * DIMK;
        p = wv + (size_t)r * DIMK;
        zero = (r >= VCOLS);
    }

    float4 v[3];
    float s = 0.f;
    if (!zero) {
#pragma unroll
        for (int j = 0; j < 3; j++) {
            v[j] = *(const float4*)(p + j * 256 + l64 * 4);
            s += v[j].x * v[j].x + v[j].y * v[j].y + v[j].z * v[j].z + v[j].w * v[j].w;
        }
    } else {
#pragma unroll
        for (int j = 0; j < 3; j++) v[j] = make_float4(0.f, 0.f, 0.f, 0.f);
    }
    for (int o = 16; o; o >>= 1) s += __shfl_xor_sync(0xffffffffu, s, o);
    __shared__ float sm[8];
    if ((tid & 31) == 0) sm[tid >> 5] = s;
    __syncthreads();
    const float tot = sm[sub * 2] + sm[sub * 2 + 1];
    const float scale = zero ? 0.f : (1.f / fmaxf(sqrtf(tot), 1e-12f));

#pragma unroll
    for (int j = 0; j < 3; j++) {
        __half2 h0 = __floats2half2_rn(v[j].x * scale, v[j].y * scale);
        __half2 h1 = __floats2half2_rn(v[j].z * scale, v[j].w * scale);
        uint2 pk = make_uint2(*(uint32_t*)&h0, *(uint32_t*)&h1);
        *(uint2*)(q + j * 256 + l64 * 4) = pk;
    }
}

// ---------------------------------------------------------------------------
// fp16 GEMM (r9-proven): m16n8k16 f32.f16.f16.f32 + ldmatrix + 4-stage
// cp.async + register-level fragment double-buffering. 128x256 tile / CTA.
// Epilogue: half2 logits -> g_scr, exp partials -> g_partials.
// ---------------------------------------------------------------------------
__global__ void __launch_bounds__(256, 1) gemm_kernel() {
    extern __shared__ __align__(1024) char smem[];

    const int tid = threadIdx.x;
    const int w = tid >> 5, lane = tid & 31;
    const int wm = w >> 2, wn = w & 3;     // 2 x 4 warp grid
    const int m0 = blockIdx.x * BM;        // m fastest: L2-friendly waves
    const int n0 = blockIdx.y * BN;
    const uint32_t sbase = smem_u32(smem);

    const __half* Ag = g_xn + (size_t)m0 * DIMK;
    const __half* Bg = g_wn + (size_t)n0 * DIMK;

    auto load_chunk = [&](int slot, int k0) {
        uint32_t sA = sbase + slot * STAGE_BYTES;
        uint32_t sB = sA + A_STAGE_BYTES;
#pragma unroll
        for (int i = 0; i < 4; i++) {
            int s = i * 256 + tid;
            int row = s >> 3, seg = s & 7;
            cpasync16(sA + swz(row * 128 + seg * 16),
                      Ag + (size_t)row * DIMK + k0 + seg * 8);
        }
#pragma unroll
        for (int i = 0; i < 8; i++) {
            int s = i * 256 + tid;
            int row = s >> 3, seg = s & 7;
            cpasync16(sB + swz(row * 128 + seg * 16),
                      Bg + (size_t)row * DIMK + k0 + seg * 8);
        }
        cpcommit();
    };

    float acc[4][8][4];
#pragma unroll
    for (int a = 0; a < 4; a++)
#pragma unroll
        for (int b = 0; b < 8; b++)
#pragma unroll
            for (int c = 0; c < 4; c++) acc[a][b][c] = 0.f;

    uint32_t aoff[4], boff[4];
#pragma unroll
    for (int mt = 0; mt < 4; mt++)
        aoff[mt] = (uint32_t)(wm * 64 + mt * 16 + (lane & 15)) * 128;
#pragma unroll
    for (int p = 0; p < 4; p++)
        boff[p] = (uint32_t)(wn * 64 + p * 16 + (lane & 7) + ((lane >> 4) & 1) * 8) * 128;
    const uint32_t acol = ((uint32_t)(lane >> 4)) * 16;
    const uint32_t bcol = ((uint32_t)((lane >> 3) & 1)) * 16;

    uint32_t afr[2][4][4], bfr[2][4][4];

    load_chunk(0, 0);
    load_chunk(1, KC);
    load_chunk(2, 2 * KC);

#pragma unroll 1
    for (int c = 0; c < NCH; c++) {
        if (c + 3 < NCH) load_chunk((c + 3) & 3, (c + 3) * KC);
        if (c <= 8) cpwait<3>();
        else if (c == 9) cpwait<2>();
        else if (c == 10) cpwait<1>();
        else cpwait<0>();
        __syncthreads();

        const uint32_t sA = sbase + (c & 3) * STAGE_BYTES;
        const uint32_t sB = sA + A_STAGE_BYTES;

#pragma unroll
        for (int mt = 0; mt < 4; mt++)
            ldm_x4(afr[0][mt][0], afr[0][mt][1], afr[0][mt][2], afr[0][mt][3],
                   sA + swz(aoff[mt] + acol));
#pragma unroll
        for (int p = 0; p < 4; p++)
            ldm_x4(bfr[0][p][0], bfr[0][p][1], bfr[0][p][2], bfr[0][p][3],
                   sB + swz(boff[p] + bcol));

#pragma unroll
        for (int step = 0; step < KC / 16; step++) {
            const int cur = step & 1;
            if (step < KC / 16 - 1) {
                const int nxt = cur ^ 1;
                const uint32_t kb = (uint32_t)(step + 1) * 32;
#pragma unroll
                for (int mt = 0; mt < 4; mt++)
                    ldm_x4(afr[nxt][mt][0], afr[nxt][mt][1], afr[nxt][mt][2], afr[nxt][mt][3],
                           sA + swz(aoff[mt] + kb + acol));
#pragma unroll
                for (int p = 0; p < 4; p++)
                    ldm_x4(bfr[nxt][p][0], bfr[nxt][p][1], bfr[nxt][p][2], bfr[nxt][p][3],
                           sB + swz(boff[p] + kb + bcol));
            }
#pragma unroll
            for (int mt = 0; mt < 4; mt++)
#pragma unroll
                for (int nt = 0; nt < 8; nt++) {
                    const int p = nt >> 1, sub = (nt & 1) * 2;
                    asm volatile(
                        "mma.sync.aligned.m16n8k16.row.col.f32.f16.f16.f32 "
                        "{%0,%1,%2,%3}, {%4,%5,%6,%7}, {%8,%9}, {%0,%1,%2,%3};\n"
                        : "+f"(acc[mt][nt][0]), "+f"(acc[mt][nt][1]),
                          "+f"(acc[mt][nt][2]), "+f"(acc[mt][nt][3])
                        : "r"(afr[cur][mt][0]), "r"(afr[cur][mt][1]),
                          "r"(afr[cur][mt][2]), "r"(afr[cur][mt][3]),
                          "r"(bfr[cur][p][sub]), "r"(bfr[cur][p][sub + 1]));
                }
        }
        __syncthreads();
    }

    // ---- Epilogue: half2 logits to scratch + exp partials ----
    float* red = (float*)smem;     // 128 rows x 16 slots
    const int g = lane >> 2, tig = lane & 3;
#pragma unroll
    for (int mt = 0; mt < 4; mt++)
#pragma unroll
        for (int i = 0; i < 2; i++) {
            float rp = 0.f;
            const int lr = wm * 64 + mt * 16 + g + 8 * i;
            const size_t rb = (size_t)(m0 + lr) * VPAD;
#pragma unroll
            for (int nt = 0; nt < 8; nt++) {
                const int gcol = n0 + wn * 64 + nt * 8 + 2 * tig;  // even
                float l0 = acc[mt][nt][i * 2] * 20.f;
                float l1 = acc[mt][nt][i * 2 + 1] * 20.f;
                *(__half2*)(g_scr + rb + gcol) = __floats2half2_rn(l0, l1);
                if (gcol < VCOLS)     rp += __expf(l0 - 20.f);
                if (gcol + 1 < VCOLS) rp += __expf(l1 - 20.f);
            }
            red[lr * 16 + wn * 4 + tig] = rp;
        }
    __syncthreads();
    if (tid < 128) {
        float s = 0.f;
#pragma unroll
        for (int j = 0; j < 16; j++) s += red[tid * 16 + j];
        g_partials[(size_t)(m0 + tid) * NTILES + blockIdx.y] = s;
    }
}

// ---------------------------------------------------------------------------
// Per-row logsumexp: lse = 20 + log(sum of partials). Deterministic. ~7us.
// ---------------------------------------------------------------------------
__global__ void __launch_bounds__(128) lse_kernel() {
    int row = blockIdx.x;
    float s = 0.f;
    for (int j = threadIdx.x; j < NTILES; j += 128)
        s += g_partials[(size_t)row * NTILES + j];
    for (int o = 16; o; o >>= 1) s += __shfl_xor_sync(0xffffffffu, s, o);
    __shared__ float sm[4];
    if ((threadIdx.x & 31) == 0) sm[threadIdx.x >> 5] = s;
    __syncthreads();
    if (threadIdx.x == 0)
        g_lse[row] = 20.f + logf(sm[0] + sm[1] + sm[2] + sm[3]);
}

// ---------------------------------------------------------------------------
// Fixup: HALF a row per 512-thread block (grid 2 x 4096), lse precomputed
// (no duplicated reduce, unlike r13). Pure stream:
// out = scr - lse + bias with alignment-headed float4 stores.
// ---------------------------------------------------------------------------
__global__ void __launch_bounds__(512) fixup_kernel(float* __restrict__ out,
                                                    const float* __restrict__ bias) {
    const int row = blockIdx.y;
    const int tid = threadIdx.x;
    const float lse = g_lse[row];

    // Column range for this half.
    const int c0 = blockIdx.x ? (VCOLS / 2) : 0;       // 0 or 25128 (mult of 4)
    const int c1 = blockIdx.x ? VCOLS : (VCOLS / 2);

    const __half* ps = g_scr + (size_t)row * VPAD;
    float* po = out + (size_t)row * VCOLS;

    // head: scalar cols until po+c0+head is 16B aligned
    const int head = (4 - (int)(((uintptr_t)(po + c0) >> 2) & 3)) & 3;
    if (tid < head && c0 + tid < c1) {
        const int col = c0 + tid;
        po[col] = __half2float(__ldcs(ps + col)) - lse + __ldg(bias + col);
    }
    const int count4 = (c1 - c0 - head) >> 2;
    const int tail0 = c0 + head + count4 * 4;
    if (tid < c1 - tail0) {
        const int col = tail0 + tid;
        po[col] = __half2float(__ldcs(ps + col)) - lse + __ldg(bias + col);
    }

    const int colbase = c0 + head;
    if ((colbase & 1) == 0) {
        // scratch cols even: half2 loads
#pragma unroll 2
        for (int i = tid; i < count4; i += 512) {
            const int col = colbase + i * 4;
            float2 a = __half22float2(__ldcs((const __half2*)(ps + col)));
            float2 b = __half22float2(__ldcs((const __half2*)(ps + col + 2)));
            float4 o4;
            o4.x = a.x - lse + __ldg(bias + col);
            o4.y = a.y - lse + __ldg(bias + col + 1);
            o4.z = b.x - lse + __ldg(bias + col + 2);
            o4.w = b.y - lse + __ldg(bias + col + 3);
            *(float4*)(po + col) = o4;
        }
    } else {
        // odd base: scalar half loads, vector store
#pragma unroll 2
        for (int i = tid; i < count4; i += 512) {
            const int col = colbase + i * 4;
            float4 o4;
            o4.x = __half2float(__ldcs(ps + col))     - lse + __ldg(bias + col);
            o4.y = __half2float(__ldcs(ps + col + 1)) - lse + __ldg(bias + col + 1);
            o4.z = __half2float(__ldcs(ps + col + 2)) - lse + __ldg(bias + col + 2);
            o4.w = __half2float(__ldcs(ps + col + 3)) - lse + __ldg(bias + col + 3);
            *(float4*)(po + col) = o4;
        }
    }
}

extern "C" void kernel_launch(void* const* d_in, const int* in_sizes, int n_in,
                              void* d_out, int out_size) {
    const float* x    = (const float*)d_in[0];  // [2,2048,768]
    const float* wv   = (const float*)d_in[1];  // [50257,768]
    const float* bias = (const float*)d_in[2];  // [50257]
    float* out = (float*)d_out;                 // [2,2048,50257] fp32

    cudaFuncSetAttribute(gemm_kernel, cudaFuncAttributeMaxDynamicSharedMemorySize, DSMEM);

    norm_rows_kernel<<<(MROWS + VPAD) / 4, 256>>>(x, wv);
    gemm_kernel<<<dim3(MROWS / BM, NTILES), 256, DSMEM>>>();
    lse_kernel<<<MROWS, 128>>>();
    fixup_kernel<<<dim3(2, MROWS), 512>>>(out, bias);
}

// round 16
// speedup vs baseline: 2.3227x; 1.0015x over previous
#include <cuda_runtime.h>
#include <cuda_fp16.h>
#include <cstdint>

#define DIMK 768
#define MROWS 4096
#define VCOLS 50257
#define VPAD 50432            // padded vocab = 197 * 256 (even)
#define BM 128
#define BN 256
#define KC 64                 // K elems per stage: 64 half = 128B rows (SW128)
#define NCH (DIMK / KC)       // 12
#define NTILES (VPAD / BN)    // 197
#define A_STAGE_BYTES (BM * 128)      // 16 KB
#define B_STAGE_BYTES (BN * 128)      // 32 KB
#define STAGE_BYTES (A_STAGE_BYTES + B_STAGE_BYTES)
#define DSMEM (4 * STAGE_BYTES)       // 192 KB

// Scratch (device globals: allocation-free rule)
__device__ __half g_xn[(size_t)MROWS * DIMK];
__device__ __half g_wn[(size_t)VPAD * DIMK];
__device__ __half g_scr[(size_t)MROWS * VPAD];      // fp16 logits scratch
__device__ float g_partials[(size_t)MROWS * NTILES];
__device__ float g_lse[MROWS];

__device__ __forceinline__ uint32_t smem_u32(const void* p) {
    uint32_t a;
    asm("{ .reg .u64 t; cvta.to.shared.u64 t, %1; cvt.u32.u64 %0, t; }" : "=r"(a) : "l"(p));
    return a;
}
__device__ __forceinline__ uint32_t swz(uint32_t x) { return x ^ ((x >> 3) & 0x70); }

template <int N>
__device__ __forceinline__ void cpwait() {
    asm volatile("cp.async.wait_group %0;" :: "n"(N) : "memory");
}
__device__ __forceinline__ void cpcommit() {
    asm volatile("cp.async.commit_group;" ::: "memory");
}
__device__ __forceinline__ void cpasync16(uint32_t s, const void* g) {
    asm volatile("cp.async.cg.shared.global [%0], [%1], 16;" :: "r"(s), "l"(g) : "memory");
}
__device__ __forceinline__ void ldm_x4(uint32_t& r0, uint32_t& r1, uint32_t& r2,
                                       uint32_t& r3, uint32_t addr) {
    asm volatile("ldmatrix.sync.aligned.m8n8.x4.shared.b16 {%0,%1,%2,%3}, [%4];"
                 : "=r"(r0), "=r"(r1), "=r"(r2), "=r"(r3) : "r"(addr));
}

// ---------------------------------------------------------------------------
// Row L2-normalize: 4 rows/block, 64 threads/row, single pass, fp16 out.
// ---------------------------------------------------------------------------
__global__ void __launch_bounds__(256) norm_rows_kernel(const float* __restrict__ x,
                                                        const float* __restrict__ wv) {
    const int tid = threadIdx.x;
    const int sub = tid >> 6;
    const int l64 = tid & 63;
    const int row = blockIdx.x * 4 + sub;

    const float* p;
    __half* q;
    bool zero = false;
    if (row < MROWS) {
        p = x + (size_t)row * DIMK;
        q = g_xn + (size_t)row * DIMK;
    } else {
        int r = row - MROWS;
        q = g_wn + (size_t)r * DIMK;
        p = wv + (size_t)r * DIMK;
        zero = (r >= VCOLS);
    }

    float4 v[3];
    float s = 0.f;
    if (!zero) {
#pragma unroll
        for (int j = 0; j < 3; j++) {
            v[j] = *(const float4*)(p + j * 256 + l64 * 4);
            s += v[j].x * v[j].x + v[j].y * v[j].y + v[j].z * v[j].z + v[j].w * v[j].w;
        }
    } else {
#pragma unroll
        for (int j = 0; j < 3; j++) v[j] = make_float4(0.f, 0.f, 0.f, 0.f);
    }
    for (int o = 16; o; o >>= 1) s += __shfl_xor_sync(0xffffffffu, s, o);
    __shared__ float sm[8];
    if ((tid & 31) == 0) sm[tid >> 5] = s;
    __syncthreads();
    const float tot = sm[sub * 2] + sm[sub * 2 + 1];
    const float scale = zero ? 0.f : (1.f / fmaxf(sqrtf(tot), 1e-12f));

#pragma unroll
    for (int j = 0; j < 3; j++) {
        __half2 h0 = __floats2half2_rn(v[j].x * scale, v[j].y * scale);
        __half2 h1 = __floats2half2_rn(v[j].z * scale, v[j].w * scale);
        uint2 pk = make_uint2(*(uint32_t*)&h0, *(uint32_t*)&h1);
        *(uint2*)(q + j * 256 + l64 * 4) = pk;
    }
}

// ---------------------------------------------------------------------------
// fp16 GEMM (r9-proven): m16n8k16 f32.f16.f16.f32 + ldmatrix + 4-stage
// cp.async + register-level fragment double-buffering. 128x256 tile / CTA.
// Epilogue: half2 logits -> g_scr, exp partials -> g_partials.
// ---------------------------------------------------------------------------
__global__ void __launch_bounds__(256, 1) gemm_kernel() {
    extern __shared__ __align__(1024) char smem[];

    const int tid = threadIdx.x;
    const int w = tid >> 5, lane = tid & 31;
    const int wm = w >> 2, wn = w & 3;     // 2 x 4 warp grid
    const int m0 = blockIdx.x * BM;        // m fastest: L2-friendly waves
    const int n0 = blockIdx.y * BN;
    const uint32_t sbase = smem_u32(smem);

    const __half* Ag = g_xn + (size_t)m0 * DIMK;
    const __half* Bg = g_wn + (size_t)n0 * DIMK;

    auto load_chunk = [&](int slot, int k0) {
        uint32_t sA = sbase + slot * STAGE_BYTES;
        uint32_t sB = sA + A_STAGE_BYTES;
#pragma unroll
        for (int i = 0; i < 4; i++) {
            int s = i * 256 + tid;
            int row = s >> 3, seg = s & 7;
            cpasync16(sA + swz(row * 128 + seg * 16),
                      Ag + (size_t)row * DIMK + k0 + seg * 8);
        }
#pragma unroll
        for (int i = 0; i < 8; i++) {
            int s = i * 256 + tid;
            int row = s >> 3, seg = s & 7;
            cpasync16(sB + swz(row * 128 + seg * 16),
                      Bg + (size_t)row * DIMK + k0 + seg * 8);
        }
        cpcommit();
    };

    float acc[4][8][4];
#pragma unroll
    for (int a = 0; a < 4; a++)
#pragma unroll
        for (int b = 0; b < 8; b++)
#pragma unroll
            for (int c = 0; c < 4; c++) acc[a][b][c] = 0.f;

    uint32_t aoff[4], boff[4];
#pragma unroll
    for (int mt = 0; mt < 4; mt++)
        aoff[mt] = (uint32_t)(wm * 64 + mt * 16 + (lane & 15)) * 128;
#pragma unroll
    for (int p = 0; p < 4; p++)
        boff[p] = (uint32_t)(wn * 64 + p * 16 + (lane & 7) + ((lane >> 4) & 1) * 8) * 128;
    const uint32_t acol = ((uint32_t)(lane >> 4)) * 16;
    const uint32_t bcol = ((uint32_t)((lane >> 3) & 1)) * 16;

    uint32_t afr[2][4][4], bfr[2][4][4];

    load_chunk(0, 0);
    load_chunk(1, KC);
    load_chunk(2, 2 * KC);

#pragma unroll 1
    for (int c = 0; c < NCH; c++) {
        if (c + 3 < NCH) load_chunk((c + 3) & 3, (c + 3) * KC);
        if (c <= 8) cpwait<3>();
        else if (c == 9) cpwait<2>();
        else if (c == 10) cpwait<1>();
        else cpwait<0>();
        __syncthreads();

        const uint32_t sA = sbase + (c & 3) * STAGE_BYTES;
        const uint32_t sB = sA + A_STAGE_BYTES;

#pragma unroll
        for (int mt = 0; mt < 4; mt++)
            ldm_x4(afr[0][mt][0], afr[0][mt][1], afr[0][mt][2], afr[0][mt][3],
                   sA + swz(aoff[mt] + acol));
#pragma unroll
        for (int p = 0; p < 4; p++)
            ldm_x4(bfr[0][p][0], bfr[0][p][1], bfr[0][p][2], bfr[0][p][3],
                   sB + swz(boff[p] + bcol));

#pragma unroll
        for (int step = 0; step < KC / 16; step++) {
            const int cur = step & 1;
            if (step < KC / 16 - 1) {
                const int nxt = cur ^ 1;
                const uint32_t kb = (uint32_t)(step + 1) * 32;
#pragma unroll
                for (int mt = 0; mt < 4; mt++)
                    ldm_x4(afr[nxt][mt][0], afr[nxt][mt][1], afr[nxt][mt][2], afr[nxt][mt][3],
                           sA + swz(aoff[mt] + kb + acol));
#pragma unroll
                for (int p = 0; p < 4; p++)
                    ldm_x4(bfr[nxt][p][0], bfr[nxt][p][1], bfr[nxt][p][2], bfr[nxt][p][3],
                           sB + swz(boff[p] + kb + bcol));
            }
#pragma unroll
            for (int mt = 0; mt < 4; mt++)
#pragma unroll
                for (int nt = 0; nt < 8; nt++) {
                    const int p = nt >> 1, sub = (nt & 1) * 2;
                    asm volatile(
                        "mma.sync.aligned.m16n8k16.row.col.f32.f16.f16.f32 "
                        "{%0,%1,%2,%3}, {%4,%5,%6,%7}, {%8,%9}, {%0,%1,%2,%3};\n"
                        : "+f"(acc[mt][nt][0]), "+f"(acc[mt][nt][1]),
                          "+f"(acc[mt][nt][2]), "+f"(acc[mt][nt][3])
                        : "r"(afr[cur][mt][0]), "r"(afr[cur][mt][1]),
                          "r"(afr[cur][mt][2]), "r"(afr[cur][mt][3]),
                          "r"(bfr[cur][p][sub]), "r"(bfr[cur][p][sub + 1]));
                }
        }
        __syncthreads();
    }

    // ---- Epilogue: half2 logits to scratch + exp partials ----
    float* red = (float*)smem;     // 128 rows x 16 slots
    const int g = lane >> 2, tig = lane & 3;
#pragma unroll
    for (int mt = 0; mt < 4; mt++)
#pragma unroll
        for (int i = 0; i < 2; i++) {
            float rp = 0.f;
            const int lr = wm * 64 + mt * 16 + g + 8 * i;
            const size_t rb = (size_t)(m0 + lr) * VPAD;
#pragma unroll
            for (int nt = 0; nt < 8; nt++) {
                const int gcol = n0 + wn * 64 + nt * 8 + 2 * tig;  // even
                float l0 = acc[mt][nt][i * 2] * 20.f;
                float l1 = acc[mt][nt][i * 2 + 1] * 20.f;
                *(__half2*)(g_scr + rb + gcol) = __floats2half2_rn(l0, l1);
                if (gcol < VCOLS)     rp += __expf(l0 - 20.f);
                if (gcol + 1 < VCOLS) rp += __expf(l1 - 20.f);
            }
            red[lr * 16 + wn * 4 + tig] = rp;
        }
    __syncthreads();
    if (tid < 128) {
        float s = 0.f;
#pragma unroll
        for (int j = 0; j < 16; j++) s += red[tid * 16 + j];
        g_partials[(size_t)(m0 + tid) * NTILES + blockIdx.y] = s;
    }
}

// ---------------------------------------------------------------------------
// Per-row logsumexp: lse = 20 + log(sum of partials). Deterministic. ~7us.
// ---------------------------------------------------------------------------
__global__ void __launch_bounds__(128) lse_kernel() {
    int row = blockIdx.x;
    float s = 0.f;
    for (int j = threadIdx.x; j < NTILES; j += 128)
        s += g_partials[(size_t)row * NTILES + j];
    for (int o = 16; o; o >>= 1) s += __shfl_xor_sync(0xffffffffu, s, o);
    __shared__ float sm[4];
    if ((threadIdx.x & 31) == 0) sm[threadIdx.x >> 5] = s;
    __syncthreads();
    if (threadIdx.x == 0)
        g_lse[row] = 20.f + logf(sm[0] + sm[1] + sm[2] + sm[3]);
}

// ---------------------------------------------------------------------------
// Fixup: HALF a row per 512-thread block (grid 2 x 4096), lse precomputed.
// out = scr - lse + bias; WRITE-THROUGH stores (keep L2 for the read stream).
// ---------------------------------------------------------------------------
__global__ void __launch_bounds__(512) fixup_kernel(float* __restrict__ out,
                                                    const float* __restrict__ bias) {
    const int row = blockIdx.y;
    const int tid = threadIdx.x;
    const float lse = g_lse[row];

    // Column range for this half.
    const int c0 = blockIdx.x ? (VCOLS / 2) : 0;       // 0 or 25128 (mult of 4)
    const int c1 = blockIdx.x ? VCOLS : (VCOLS / 2);

    const __half* ps = g_scr + (size_t)row * VPAD;
    float* po = out + (size_t)row * VCOLS;

    // head: scalar cols until po+c0+head is 16B aligned
    const int head = (4 - (int)(((uintptr_t)(po + c0) >> 2) & 3)) & 3;
    if (tid < head && c0 + tid < c1) {
        const int col = c0 + tid;
        __stwt(po + col, __half2float(__ldcs(ps + col)) - lse + __ldg(bias + col));
    }
    const int count4 = (c1 - c0 - head) >> 2;
    const int tail0 = c0 + head + count4 * 4;
    if (tid < c1 - tail0) {
        const int col = tail0 + tid;
        __stwt(po + col, __half2float(__ldcs(ps + col)) - lse + __ldg(bias + col));
    }

    const int colbase = c0 + head;
    if ((colbase & 1) == 0) {
        // scratch cols even: half2 loads
#pragma unroll 2
        for (int i = tid; i < count4; i += 512) {
            const int col = colbase + i * 4;
            float2 a = __half22float2(__ldcs((const __half2*)(ps + col)));
            float2 b = __half22float2(__ldcs((const __half2*)(ps + col + 2)));
            float4 o4;
            o4.x = a.x - lse + __ldg(bias + col);
            o4.y = a.y - lse + __ldg(bias + col + 1);
            o4.z = b.x - lse + __ldg(bias + col + 2);
            o4.w = b.y - lse + __ldg(bias + col + 3);
            __stwt((float4*)(po + col), o4);
        }
    } else {
        // odd base: scalar half loads, vector store
#pragma unroll 2
        for (int i = tid; i < count4; i += 512) {
            const int col = colbase + i * 4;
            float4 o4;
            o4.x = __half2float(__ldcs(ps + col))     - lse + __ldg(bias + col);
            o4.y = __half2float(__ldcs(ps + col + 1)) - lse + __ldg(bias + col + 1);
            o4.z = __half2float(__ldcs(ps + col + 2)) - lse + __ldg(bias + col + 2);
            o4.w = __half2float(__ldcs(ps + col + 3)) - lse + __ldg(bias + col + 3);
            __stwt((float4*)(po + col), o4);
        }
    }
}

extern "C" void kernel_launch(void* const* d_in, const int* in_sizes, int n_in,
                              void* d_out, int out_size) {
    const float* x    = (const float*)d_in[0];  // [2,2048,768]
    const float* wv   = (const float*)d_in[1];  // [50257,768]
    const float* bias = (const float*)d_in[2];  // [50257]
    float* out = (float*)d_out;                 // [2,2048,50257] fp32

    cudaFuncSetAttribute(gemm_kernel, cudaFuncAttributeMaxDynamicSharedMemorySize, DSMEM);

    norm_rows_kernel<<<(MROWS + VPAD) / 4, 256>>>(x, wv);
    gemm_kernel<<<dim3(MROWS / BM, NTILES), 256, DSMEM>>>();
    lse_kernel<<<MROWS, 128>>>();
    fixup_kernel<<<dim3(2, MROWS), 512>>>(out, bias);
}

// round 17
// speedup vs baseline: 2.3303x; 1.0033x over previous
#include <cuda_runtime.h>
#include <cuda_fp16.h>
#include <cstdint>

#define DIMK 768
#define MROWS 4096
#define VCOLS 50257
#define VPAD 50432            // padded vocab = 197 * 256 (even)
#define BM 128
#define BN 256
#define KC 64                 // K elems per stage: 64 half = 128B rows (SW128)
#define NCH (DIMK / KC)       // 12
#define NTILES (VPAD / BN)    // 197
#define A_STAGE_BYTES (BM * 128)      // 16 KB
#define B_STAGE_BYTES (BN * 128)      // 32 KB
#define STAGE_BYTES (A_STAGE_BYTES + B_STAGE_BYTES)
#define DSMEM (4 * STAGE_BYTES)       // 192 KB

// Scratch (device globals: allocation-free rule)
__device__ __half g_xn[(size_t)MROWS * DIMK];
__device__ __half g_wn[(size_t)VPAD * DIMK];
__device__ __half g_scr[(size_t)MROWS * VPAD];      // fp16 logits scratch
__device__ float g_partials[(size_t)MROWS * NTILES];
__device__ float g_lse[MROWS];

__device__ __forceinline__ uint32_t smem_u32(const void* p) {
    uint32_t a;
    asm("{ .reg .u64 t; cvta.to.shared.u64 t, %1; cvt.u32.u64 %0, t; }" : "=r"(a) : "l"(p));
    return a;
}
__device__ __forceinline__ uint32_t swz(uint32_t x) { return x ^ ((x >> 3) & 0x70); }

template <int N>
__device__ __forceinline__ void cpwait() {
    asm volatile("cp.async.wait_group %0;" :: "n"(N) : "memory");
}
__device__ __forceinline__ void cpcommit() {
    asm volatile("cp.async.commit_group;" ::: "memory");
}
__device__ __forceinline__ void cpasync16(uint32_t s, const void* g) {
    asm volatile("cp.async.cg.shared.global [%0], [%1], 16;" :: "r"(s), "l"(g) : "memory");
}
__device__ __forceinline__ void ldm_x4(uint32_t& r0, uint32_t& r1, uint32_t& r2,
                                       uint32_t& r3, uint32_t addr) {
    asm volatile("ldmatrix.sync.aligned.m8n8.x4.shared.b16 {%0,%1,%2,%3}, [%4];"
                 : "=r"(r0), "=r"(r1), "=r"(r2), "=r"(r3) : "r"(addr));
}

// ---------------------------------------------------------------------------
// Row L2-normalize: 4 rows/block, 64 threads/row, single pass, fp16 out.
// ---------------------------------------------------------------------------
__global__ void __launch_bounds__(256) norm_rows_kernel(const float* __restrict__ x,
                                                        const float* __restrict__ wv) {
    const int tid = threadIdx.x;
    const int sub = tid >> 6;
    const int l64 = tid & 63;
    const int row = blockIdx.x * 4 + sub;

    const float* p;
    __half* q;
    bool zero = false;
    if (row < MROWS) {
        p = x + (size_t)row * DIMK;
        q = g_xn + (size_t)row * DIMK;
    } else {
        int r = row - MROWS;
        q = g_wn + (size_t)r * DIMK;
        p = wv + (size_t)r * DIMK;
        zero = (r >= VCOLS);
    }

    float4 v[3];
    float s = 0.f;
    if (!zero) {
#pragma unroll
        for (int j = 0; j < 3; j++) {
            v[j] = *(const float4*)(p + j * 256 + l64 * 4);
            s += v[j].x * v[j].x + v[j].y * v[j].y + v[j].z * v[j].z + v[j].w * v[j].w;
        }
    } else {
#pragma unroll
        for (int j = 0; j < 3; j++) v[j] = make_float4(0.f, 0.f, 0.f, 0.f);
    }
    for (int o = 16; o; o >>= 1) s += __shfl_xor_sync(0xffffffffu, s, o);
    __shared__ float sm[8];
    if ((tid & 31) == 0) sm[tid >> 5] = s;
    __syncthreads();
    const float tot = sm[sub * 2] + sm[sub * 2 + 1];
    const float scale = zero ? 0.f : (1.f / fmaxf(sqrtf(tot), 1e-12f));

#pragma unroll
    for (int j = 0; j < 3; j++) {
        __half2 h0 = __floats2half2_rn(v[j].x * scale, v[j].y * scale);
        __half2 h1 = __floats2half2_rn(v[j].z * scale, v[j].w * scale);
        uint2 pk = make_uint2(*(uint32_t*)&h0, *(uint32_t*)&h1);
        *(uint2*)(q + j * 256 + l64 * 4) = pk;
    }
}

// ---------------------------------------------------------------------------
// fp16 GEMM (r9-proven): m16n8k16 f32.f16.f16.f32 + ldmatrix + 4-stage
// cp.async + register-level fragment double-buffering. 128x256 tile / CTA.
// Epilogue: half2 logits -> g_scr, exp partials -> g_partials.
// ---------------------------------------------------------------------------
__global__ void __launch_bounds__(256, 1) gemm_kernel() {
    extern __shared__ __align__(1024) char smem[];

    const int tid = threadIdx.x;
    const int w = tid >> 5, lane = tid & 31;
    const int wm = w >> 2, wn = w & 3;     // 2 x 4 warp grid
    const int m0 = blockIdx.x * BM;        // m fastest: L2-friendly waves
    const int n0 = blockIdx.y * BN;
    const uint32_t sbase = smem_u32(smem);

    const __half* Ag = g_xn + (size_t)m0 * DIMK;
    const __half* Bg = g_wn + (size_t)n0 * DIMK;

    auto load_chunk = [&](int slot, int k0) {
        uint32_t sA = sbase + slot * STAGE_BYTES;
        uint32_t sB = sA + A_STAGE_BYTES;
#pragma unroll
        for (int i = 0; i < 4; i++) {
            int s = i * 256 + tid;
            int row = s >> 3, seg = s & 7;
            cpasync16(sA + swz(row * 128 + seg * 16),
                      Ag + (size_t)row * DIMK + k0 + seg * 8);
        }
#pragma unroll
        for (int i = 0; i < 8; i++) {
            int s = i * 256 + tid;
            int row = s >> 3, seg = s & 7;
            cpasync16(sB + swz(row * 128 + seg * 16),
                      Bg + (size_t)row * DIMK + k0 + seg * 8);
        }
        cpcommit();
    };

    float acc[4][8][4];
#pragma unroll
    for (int a = 0; a < 4; a++)
#pragma unroll
        for (int b = 0; b < 8; b++)
#pragma unroll
            for (int c = 0; c < 4; c++) acc[a][b][c] = 0.f;

    uint32_t aoff[4], boff[4];
#pragma unroll
    for (int mt = 0; mt < 4; mt++)
        aoff[mt] = (uint32_t)(wm * 64 + mt * 16 + (lane & 15)) * 128;
#pragma unroll
    for (int p = 0; p < 4; p++)
        boff[p] = (uint32_t)(wn * 64 + p * 16 + (lane & 7) + ((lane >> 4) & 1) * 8) * 128;
    const uint32_t acol = ((uint32_t)(lane >> 4)) * 16;
    const uint32_t bcol = ((uint32_t)((lane >> 3) & 1)) * 16;

    uint32_t afr[2][4][4], bfr[2][4][4];

    load_chunk(0, 0);
    load_chunk(1, KC);
    load_chunk(2, 2 * KC);

#pragma unroll 1
    for (int c = 0; c < NCH; c++) {
        if (c + 3 < NCH) load_chunk((c + 3) & 3, (c + 3) * KC);
        if (c <= 8) cpwait<3>();
        else if (c == 9) cpwait<2>();
        else if (c == 10) cpwait<1>();
        else cpwait<0>();
        __syncthreads();

        const uint32_t sA = sbase + (c & 3) * STAGE_BYTES;
        const uint32_t sB = sA + A_STAGE_BYTES;

#pragma unroll
        for (int mt = 0; mt < 4; mt++)
            ldm_x4(afr[0][mt][0], afr[0][mt][1], afr[0][mt][2], afr[0][mt][3],
                   sA + swz(aoff[mt] + acol));
#pragma unroll
        for (int p = 0; p < 4; p++)
            ldm_x4(bfr[0][p][0], bfr[0][p][1], bfr[0][p][2], bfr[0][p][3],
                   sB + swz(boff[p] + bcol));

#pragma unroll
        for (int step = 0; step < KC / 16; step++) {
            const int cur = step & 1;
            if (step < KC / 16 - 1) {
                const int nxt = cur ^ 1;
                const uint32_t kb = (uint32_t)(step + 1) * 32;
#pragma unroll
                for (int mt = 0; mt < 4; mt++)
                    ldm_x4(afr[nxt][mt][0], afr[nxt][mt][1], afr[nxt][mt][2], afr[nxt][mt][3],
                           sA + swz(aoff[mt] + kb + acol));
#pragma unroll
                for (int p = 0; p < 4; p++)
                    ldm_x4(bfr[nxt][p][0], bfr[nxt][p][1], bfr[nxt][p][2], bfr[nxt][p][3],
                           sB + swz(boff[p] + kb + bcol));
            }
#pragma unroll
            for (int mt = 0; mt < 4; mt++)
#pragma unroll
                for (int nt = 0; nt < 8; nt++) {
                    const int p = nt >> 1, sub = (nt & 1) * 2;
                    asm volatile(
                        "mma.sync.aligned.m16n8k16.row.col.f32.f16.f16.f32 "
                        "{%0,%1,%2,%3}, {%4,%5,%6,%7}, {%8,%9}, {%0,%1,%2,%3};\n"
                        : "+f"(acc[mt][nt][0]), "+f"(acc[mt][nt][1]),
                          "+f"(acc[mt][nt][2]), "+f"(acc[mt][nt][3])
                        : "r"(afr[cur][mt][0]), "r"(afr[cur][mt][1]),
                          "r"(afr[cur][mt][2]), "r"(afr[cur][mt][3]),
                          "r"(bfr[cur][p][sub]), "r"(bfr[cur][p][sub + 1]));
                }
        }
        __syncthreads();
    }

    // ---- Epilogue: half2 logits to scratch + exp partials ----
    float* red = (float*)smem;     // 128 rows x 16 slots
    const int g = lane >> 2, tig = lane & 3;
#pragma unroll
    for (int mt = 0; mt < 4; mt++)
#pragma unroll
        for (int i = 0; i < 2; i++) {
            float rp = 0.f;
            const int lr = wm * 64 + mt * 16 + g + 8 * i;
            const size_t rb = (size_t)(m0 + lr) * VPAD;
#pragma unroll
            for (int nt = 0; nt < 8; nt++) {
                const int gcol = n0 + wn * 64 + nt * 8 + 2 * tig;  // even
                float l0 = acc[mt][nt][i * 2] * 20.f;
                float l1 = acc[mt][nt][i * 2 + 1] * 20.f;
                *(__half2*)(g_scr + rb + gcol) = __floats2half2_rn(l0, l1);
                if (gcol < VCOLS)     rp += __expf(l0 - 20.f);
                if (gcol + 1 < VCOLS) rp += __expf(l1 - 20.f);
            }
            red[lr * 16 + wn * 4 + tig] = rp;
        }
    __syncthreads();
    if (tid < 128) {
        float s = 0.f;
#pragma unroll
        for (int j = 0; j < 16; j++) s += red[tid * 16 + j];
        g_partials[(size_t)(m0 + tid) * NTILES + blockIdx.y] = s;
    }
}

// ---------------------------------------------------------------------------
// Per-row logsumexp: lse = 20 + log(sum of partials). Deterministic. ~7us.
// ---------------------------------------------------------------------------
__global__ void __launch_bounds__(128) lse_kernel() {
    int row = blockIdx.x;
    float s = 0.f;
    for (int j = threadIdx.x; j < NTILES; j += 128)
        s += g_partials[(size_t)row * NTILES + j];
    for (int o = 16; o; o >>= 1) s += __shfl_xor_sync(0xffffffffu, s, o);
    __shared__ float sm[4];
    if ((threadIdx.x & 31) == 0) sm[threadIdx.x >> 5] = s;
    __syncthreads();
    if (threadIdx.x == 0)
        g_lse[row] = 20.f + logf(sm[0] + sm[1] + sm[2] + sm[3]);
}

// ---------------------------------------------------------------------------
// Fixup: HALF a row per 512-thread block (grid 2 x 4096), lse precomputed.
// ILP-batched (unroll 2, hoisted loads); head==0 path uses 8B scratch loads.
// out = scr - lse + bias; write-through float4 stores.
// ---------------------------------------------------------------------------
__global__ void __launch_bounds__(512) fixup_kernel(float* __restrict__ out,
                                                    const float* __restrict__ bias) {
    const int row = blockIdx.y;
    const int tid = threadIdx.x;
    const float lse = g_lse[row];

    const int c0 = blockIdx.x ? (VCOLS / 2) : 0;       // 0 or 25128 (mult of 8)
    const int c1 = blockIdx.x ? VCOLS : (VCOLS / 2);

    const __half* ps = g_scr + (size_t)row * VPAD;
    float* po = out + (size_t)row * VCOLS;

    const int head = (4 - (int)(((uintptr_t)(po + c0) >> 2) & 3)) & 3;
    if (tid < head && c0 + tid < c1) {
        const int col = c0 + tid;
        __stwt(po + col, __half2float(__ldcs(ps + col)) - lse + __ldg(bias + col));
    }
    const int count4 = (c1 - c0 - head) >> 2;
    const int tail0 = c0 + head + count4 * 4;
    if (tid < c1 - tail0) {
        const int col = tail0 + tid;
        __stwt(po + col, __half2float(__ldcs(ps + col)) - lse + __ldg(bias + col));
    }

    const int colbase = c0 + head;

    auto emit = [&](int col, float2 a, float2 b) {
        float4 o4;
        o4.x = a.x - lse + __ldg(bias + col);
        o4.y = a.y - lse + __ldg(bias + col + 1);
        o4.z = b.x - lse + __ldg(bias + col + 2);
        o4.w = b.y - lse + __ldg(bias + col + 3);
        __stwt((float4*)(po + col), o4);
    };

    if (head == 0) {
        // colbase % 4 == 0: 8B-aligned scratch loads, unroll-2 with hoisted loads
        int i = tid;
        for (; i + 512 < count4; i += 1024) {
            const int colA = colbase + i * 4;
            const int colB = colbase + (i + 512) * 4;
            uint2 ra = __ldcs((const uint2*)(ps + colA));
            uint2 rb = __ldcs((const uint2*)(ps + colB));
            emit(colA, __half22float2(*(__half2*)&ra.x), __half22float2(*(__half2*)&ra.y));
            emit(colB, __half22float2(*(__half2*)&rb.x), __half22float2(*(__half2*)&rb.y));
        }
        for (; i < count4; i += 512) {
            const int col = colbase + i * 4;
            uint2 r = __ldcs((const uint2*)(ps + col));
            emit(col, __half22float2(*(__half2*)&r.x), __half22float2(*(__half2*)&r.y));
        }
    } else if ((head & 1) == 0) {
        // even base: half2 loads, unroll-2 with hoisted loads
        int i = tid;
        for (; i + 512 < count4; i += 1024) {
            const int colA = colbase + i * 4;
            const int colB = colbase + (i + 512) * 4;
            __half2 a0 = __ldcs((const __half2*)(ps + colA));
            __half2 a1 = __ldcs((const __half2*)(ps + colA + 2));
            __half2 b0 = __ldcs((const __half2*)(ps + colB));
            __half2 b1 = __ldcs((const __half2*)(ps + colB + 2));
            emit(colA, __half22float2(a0), __half22float2(a1));
            emit(colB, __half22float2(b0), __half22float2(b1));
        }
        for (; i < count4; i += 512) {
            const int col = colbase + i * 4;
            __half2 a0 = __ldcs((const __half2*)(ps + col));
            __half2 a1 = __ldcs((const __half2*)(ps + col + 2));
            emit(col, __half22float2(a0), __half22float2(a1));
        }
    } else {
        // odd base: scalar half loads, unroll-2 with hoisted loads
        int i = tid;
        for (; i + 512 < count4; i += 1024) {
            const int colA = colbase + i * 4;
            const int colB = colbase + (i + 512) * 4;
            float a0 = __half2float(__ldcs(ps + colA));
            float a1 = __half2float(__ldcs(ps + colA + 1));
            float a2 = __half2float(__ldcs(ps + colA + 2));
            float a3 = __half2float(__ldcs(ps + colA + 3));
            float b0 = __half2float(__ldcs(ps + colB));
            float b1 = __half2float(__ldcs(ps + colB + 1));
            float b2 = __half2float(__ldcs(ps + colB + 2));
            float b3 = __half2float(__ldcs(ps + colB + 3));
            emit(colA, make_float2(a0, a1), make_float2(a2, a3));
            emit(colB, make_float2(b0, b1), make_float2(b2, b3));
        }
        for (; i < count4; i += 512) {
            const int col = colbase + i * 4;
            float a0 = __half2float(__ldcs(ps + col));
            float a1 = __half2float(__ldcs(ps + col + 1));
            float a2 = __half2float(__ldcs(ps + col + 2));
            float a3 = __half2float(__ldcs(ps + col + 3));
            emit(col, make_float2(a0, a1), make_float2(a2, a3));
        }
    }
}

extern "C" void kernel_launch(void* const* d_in, const int* in_sizes, int n_in,
                              void* d_out, int out_size) {
    const float* x    = (const float*)d_in[0];  // [2,2048,768]
    const float* wv   = (const float*)d_in[1];  // [50257,768]
    const float* bias = (const float*)d_in[2];  // [50257]
    float* out = (float*)d_out;                 // [2,2048,50257] fp32

    cudaFuncSetAttribute(gemm_kernel, cudaFuncAttributeMaxDynamicSharedMemorySize, DSMEM);

    norm_rows_kernel<<<(MROWS + VPAD) / 4, 256>>>(x, wv);
    gemm_kernel<<<dim3(MROWS / BM, NTILES), 256, DSMEM>>>();
    lse_kernel<<<MROWS, 128>>>();
    fixup_kernel<<<dim3(2, MROWS), 512>>>(out, bias);
}